// round 13
// baseline (speedup 1.0000x reference)
#include <cuda_runtime.h>
#include <cuda_bf16.h>
#include <math.h>
#include <cstdint>

#define NB 32
#define CH 128
#define HW 4096           // 64*64
#define CNT 131072.0f     // NB*HW, bn population per channel
#define EPS 1e-5f
#define SP 72             // padded plane stride (PAD=4 halo each side)
#define PPN (SP*SP)       // 5184

// ---------------- scratch (device globals; no mallocs allowed) ----------------
__device__ float g_s  [NB*2*HW];      // channel mean/max planes
__device__ float g_sig[NB*HW];        // spatial-attention sigmoid map
__device__ float g_bufA[NB*CH*HW];    // sep3 dw / scratch
__device__ float g_bufB[NB*CH*HW];    // sep5 dw / scratch
__device__ float g_b1 [NB*CH*HW];     // maxpool branch
__device__ float g_b2 [NB*CH*HW];     // avgpool branch
__device__ float g_b4 [NB*CH*HW];     // sep3 branch
__device__ float g_b5 [NB*CH*HW];     // sep5 branch
__device__ float g_b6 [NB*CH*HW];     // dil3 branch
__device__ float g_b7 [NB*CH*HW];     // dil5 branch
__device__ float g_psum[NB*CH];
__device__ float g_pmax[NB*CH];
__device__ float g_att [NB*CH];
__device__ int   g_nd[CH];
__device__ int   g_winner[CH];
__device__ float g_sum[8*CH];         // bn stats slots
__device__ float g_sq [8*CH];

// ---------------- tiny helper kernels ----------------
__global__ void k_zero_stats() {
    int i = blockIdx.x*256 + threadIdx.x;
    if (i < 8*CH) { g_sum[i] = 0.f; g_sq[i] = 0.f; }
}

// ---------------- stage A: spatial attention ----------------
__global__ void k_chanstat(const float* __restrict__ x) {
    int idx = blockIdx.x*256 + threadIdx.x;       // n*HW + hw
    if (idx >= NB*HW) return;
    int n = idx >> 12, hw = idx & (HW-1);
    const float* p = x + (size_t)n*CH*HW + hw;
    float s = 0.f, m = -1e30f;
    #pragma unroll 8
    for (int c = 0; c < CH; c++) { float v = p[c*HW]; s += v; m = fmaxf(m, v); }
    g_s[n*2*HW + hw]      = s * (1.f/CH);
    g_s[n*2*HW + HW + hw] = m;
}

__global__ void k_saconv(const float* __restrict__ saw) {
    __shared__ float w[98];
    if (threadIdx.x < 98) w[threadIdx.x] = saw[threadIdx.x];
    __syncthreads();
    int n  = blockIdx.x >> 4;
    int hw = (blockIdx.x & 15) * 256 + threadIdx.x;
    int h = hw >> 6, wx = hw & 63;
    const float* sp = g_s + n*2*HW;
    float acc = 0.f;
    #pragma unroll
    for (int ic = 0; ic < 2; ic++)
        #pragma unroll
        for (int kh = 0; kh < 7; kh++) {
            int ih = h + kh - 3;
            if (ih < 0 || ih > 63) continue;
            #pragma unroll
            for (int kw = 0; kw < 7; kw++) {
                int iw = wx + kw - 3;
                if (iw >= 0 && iw <= 63)
                    acc += __ldg(&sp[ic*HW + ih*64 + iw]) * w[ic*49 + kh*7 + kw];
            }
        }
    g_sig[n*HW + hw] = 1.f / (1.f + __expf(-acc));
}

// stats of x1 = x*sig over HW per (n,c)  (x1 not materialized)
__global__ void k_x1red(const float* __restrict__ x) {
    int n = blockIdx.x >> 7, c = blockIdx.x & 127;
    size_t base = ((size_t)n*CH + c)*HW;
    const float4* sg = (const float4*)(g_sig + n*HW);
    const float4* xi = (const float4*)(x + base);
    float s = 0.f, m = -1e30f;
    for (int i = threadIdx.x; i < HW/4; i += 256) {
        float4 v = xi[i], g = sg[i];
        float a = v.x*g.x, b = v.y*g.y, cc = v.z*g.z, dd = v.w*g.w;
        s += (a+b) + (cc+dd);
        m = fmaxf(m, fmaxf(fmaxf(a,b), fmaxf(cc,dd)));
    }
    __shared__ float rs[256], rm[256];
    rs[threadIdx.x] = s; rm[threadIdx.x] = m; __syncthreads();
    for (int o = 128; o > 0; o >>= 1) {
        if (threadIdx.x < o) {
            rs[threadIdx.x] += rs[threadIdx.x + o];
            rm[threadIdx.x] = fmaxf(rm[threadIdx.x], rm[threadIdx.x + o]);
        }
        __syncthreads();
    }
    if (threadIdx.x == 0) { g_psum[n*CH+c] = rs[0]; g_pmax[n*CH+c] = rm[0]; }
}

__global__ void k_att(const float* __restrict__ fc1, const float* __restrict__ fc2) {
    int n = blockIdx.x, t = threadIdx.x;   // 128 threads
    __shared__ float m[CH], mx[CH], hm[64], hx[64];
    m[t]  = g_psum[n*CH+t] * (1.f/HW);
    mx[t] = g_pmax[n*CH+t];
    __syncthreads();
    if (t < 64) {
        float a = 0.f, b = 0.f;
        for (int c = 0; c < CH; c++) { float w = fc1[t*CH+c]; a += w*m[c]; b += w*mx[c]; }
        hm[t] = fmaxf(a, 0.f); hx[t] = fmaxf(b, 0.f);
    }
    __syncthreads();
    float a = 0.f, b = 0.f;
    for (int k = 0; k < 64; k++) { float w = fc2[t*64+k]; a += w*hm[k]; b += w*hx[k]; }
    g_att[n*CH+t] = 1.f / (1.f + __expf(-(a + b)));
}

__global__ void k_topk(const int* __restrict__ perm) {
    int c = threadIdx.x;   // 128 threads
    __shared__ float sl[CH];
    float s = 0.f;
    for (int n = 0; n < NB; n++) s += g_att[n*CH + c];
    sl[c] = s; __syncthreads();
    float v = sl[c];
    int rank = 0;
    for (int d = 0; d < CH; d++) { float u = sl[d]; rank += (u > v) || (u == v && d < c); }
    if (rank < 96) g_nd[rank] = c;
    if (c < 32) g_nd[96 + c] = perm[c];
    int win;
    if (c < 32) {
        int inv = 0;
        for (int i = 0; i < 32; i++) if (perm[i] == c) inv = i;
        win = 96 + inv;                 // perm positions are last -> always win
    } else {
        win = (rank < 96) ? rank : -1;
    }
    g_winner[c] = win;
}

// ---------------- depthwise quad helper ----------------
template<int KS, int DIL>
__device__ __forceinline__ void dw_quad(const float* __restrict__ pl, int h, int w0,
                                        const float* __restrict__ wt, float4* outv) {
    constexpr int R2 = (KS/2)*DIL;
    float a0 = 0.f, a1 = 0.f, a2 = 0.f, a3 = 0.f;
    #pragma unroll
    for (int kh = 0; kh < KS; kh++) {
        int ph = h + 4 + (kh - KS/2)*DIL;
        const float4* rp = (const float4*)&pl[ph*SP + w0];
        float buf[12];
        #pragma unroll
        for (int l = 0; l < 3; l++) {
            float4 t = rp[l];
            buf[l*4+0]=t.x; buf[l*4+1]=t.y; buf[l*4+2]=t.z; buf[l*4+3]=t.w;
        }
        #pragma unroll
        for (int kw = 0; kw < KS; kw++) {
            float wv = wt[kh*KS + kw];
            constexpr int base = 4 - R2;
            int b = base + kw*DIL;
            a0 += buf[b+0]*wv; a1 += buf[b+1]*wv; a2 += buf[b+2]*wv; a3 += buf[b+3]*wv;
        }
    }
    *outv = make_float4(a0, a1, a2, a3);
}

// ---------------- stage-1 fusion: x2 on-the-fly + pool + 4 first dws ----------
__global__ void __launch_bounds__(256) k_stage1(
        const float* __restrict__ x,
        const float* __restrict__ w3, const float* __restrict__ w5,
        const float* __restrict__ wd3, const float* __restrict__ wd5) {
    __shared__ float raw[HW];
    __shared__ float pp[PPN];
    __shared__ float red[1024];
    __shared__ float sw3[9], sw5[25], swd3[9], swd5[25];
    int n = blockIdx.x >> 7, j = blockIdx.x & 127;
    int t = threadIdx.x;
    int cin = g_nd[j];
    float av = g_att[n*CH + cin];
    if (t < 9)  sw3[t]  = w3[j*9 + t];
    if (t < 25) sw5[t]  = w5[j*25 + t];
    if (t >= 32 && t < 41)  swd3[t-32] = wd3[j*9 + (t-32)];
    if (t >= 64 && t < 89)  swd5[t-64] = wd5[j*25 + (t-64)];
    for (int i = t; i < PPN/4; i += 256) ((float4*)pp)[i] = make_float4(0,0,0,0);
    __syncthreads();
    const float4* in4 = (const float4*)(x + ((size_t)n*CH + cin)*HW);
    const float4* sg4 = (const float4*)(g_sig + n*HW);
    for (int q = t; q < 1024; q += 256) {
        float4 v = in4[q], s = sg4[q];
        v.x *= s.x*av; v.y *= s.y*av; v.z *= s.z*av; v.w *= s.w*av;
        ((float4*)raw)[q] = v;
        int h = q >> 4, c4 = (q & 15) * 4;
        float4 r = make_float4(fmaxf(v.x,0.f), fmaxf(v.y,0.f), fmaxf(v.z,0.f), fmaxf(v.w,0.f));
        *(float4*)&pp[(h+4)*SP + c4 + 4] = r;
    }
    __syncthreads();

    size_t ob = ((size_t)n*CH + j)*HW;
    float s1 = 0.f, q1 = 0.f, s2 = 0.f, q2 = 0.f;
    for (int i = t; i < HW; i += 256) {
        int h = i >> 6, w = i & 63;
        int h0 = max(h-1,0), h1 = min(h+1,63), w0 = max(w-1,0), w1 = min(w+1,63);
        float mx = -1e30f, sm = 0.f;
        for (int hh = h0; hh <= h1; hh++)
            for (int ww = w0; ww <= w1; ww++) {
                float v = raw[hh*64+ww];
                mx = fmaxf(mx, v); sm += v;
            }
        float avp = sm / (float)((h1-h0+1)*(w1-w0+1));
        g_b1[ob+i] = mx; g_b2[ob+i] = avp;
        s1 += mx; q1 += mx*mx; s2 += avp; q2 += avp*avp;
    }
    red[t] = s1; red[256+t] = q1; red[512+t] = s2; red[768+t] = q2;
    __syncthreads();
    for (int o = 128; o > 0; o >>= 1) {
        if (t < o) {
            red[t]     += red[t+o];
            red[256+t] += red[256+t+o];
            red[512+t] += red[512+t+o];
            red[768+t] += red[768+t+o];
        }
        __syncthreads();
    }
    if (t == 0) {
        atomicAdd(&g_sum[0*CH+j], red[0]);   atomicAdd(&g_sq[0*CH+j], red[256]);
        atomicAdd(&g_sum[1*CH+j], red[512]); atomicAdd(&g_sq[1*CH+j], red[768]);
    }
    for (int q = t; q < 1024; q += 256) {
        int h = q >> 4, w0 = (q & 15) * 4;
        float4 o4;
        dw_quad<3,1>(pp, h, w0, sw3,  &o4); *(float4*)&g_bufA[ob + h*64 + w0] = o4;
        dw_quad<5,1>(pp, h, w0, sw5,  &o4); *(float4*)&g_bufB[ob + h*64 + w0] = o4;
        dw_quad<3,2>(pp, h, w0, swd3, &o4); *(float4*)&g_b6 [ob + h*64 + w0] = o4;
        dw_quad<5,2>(pp, h, w0, swd5, &o4); *(float4*)&g_b7 [ob + h*64 + w0] = o4;
    }
}

// second-stage dw: in -> bn(slot)+relu -> dw(KS, dil1) -> out
template<int KS>
__global__ void __launch_bounds__(256) k_dw2(const float* __restrict__ in,
                                             const float* __restrict__ dwW,
                                             float* __restrict__ out, int slot) {
    __shared__ float pp[PPN];
    __shared__ float wt[KS*KS];
    int n = blockIdx.x >> 7, j = blockIdx.x & 127;
    int t = threadIdx.x;
    if (t < KS*KS) wt[t] = dwW[j*KS*KS + t];
    float mean = g_sum[slot*CH + j] / CNT;
    float var  = g_sq [slot*CH + j] / CNT - mean*mean;
    float rstd = rsqrtf(var + EPS);
    for (int i = t; i < PPN/4; i += 256) ((float4*)pp)[i] = make_float4(0,0,0,0);
    __syncthreads();
    const float4* in4 = (const float4*)(in + ((size_t)n*CH + j)*HW);
    for (int q = t; q < 1024; q += 256) {
        float4 v = in4[q];
        int h = q >> 4, c4 = (q & 15) * 4;
        float4 r = make_float4(fmaxf((v.x-mean)*rstd, 0.f), fmaxf((v.y-mean)*rstd, 0.f),
                               fmaxf((v.z-mean)*rstd, 0.f), fmaxf((v.w-mean)*rstd, 0.f));
        *(float4*)&pp[(h+4)*SP + c4 + 4] = r;
    }
    __syncthreads();
    size_t ob = ((size_t)n*CH + j)*HW;
    for (int q = t; q < 1024; q += 256) {
        int h = q >> 4, w0 = (q & 15) * 4;
        float4 o4;
        dw_quad<KS,1>(pp, h, w0, wt, &o4);
        *(float4*)&out[ob + h*64 + w0] = o4;
    }
}

// ---------------- tensor-core pointwise conv via mma.sync tf32 ----------------
// D[p,co] = sum_ci A[p,ci]*W[co,ci]; single tf32 pass (m16n8k8), fp32 accum.
// Block: one (n, 128-pixel tile). 8 warps = 2(m)x4(n), warp tile 64p x 32co.
#define AST 132                          // fp32 row stride (floats)
#define TILE_F (128*AST)                 // floats per tile
#define PWM_SMEM (2*TILE_F*4)            // 135168 B

__device__ __forceinline__ unsigned f2tf(float v) {
    unsigned r; asm("cvt.rna.tf32.f32 %0, %1;" : "=r"(r) : "f"(v)); return r;
}
__device__ __forceinline__ void mma_tf32(float* d, const unsigned* a, const unsigned* b) {
    asm volatile(
        "mma.sync.aligned.m16n8k8.row.col.f32.tf32.tf32.f32 "
        "{%0,%1,%2,%3}, {%4,%5,%6,%7}, {%8,%9}, {%0,%1,%2,%3};"
        : "+f"(d[0]), "+f"(d[1]), "+f"(d[2]), "+f"(d[3])
        : "r"(a[0]), "r"(a[1]), "r"(a[2]), "r"(a[3]), "r"(b[0]), "r"(b[1]));
}

__global__ void __launch_bounds__(256, 1)
k_pwm(const float* __restrict__ in, const float* __restrict__ wt,
      float* __restrict__ out, int slot) {
    extern __shared__ float smem[];
    float* As = smem;            // [p][ci], stride AST
    float* Ws = smem + TILE_F;   // [co][ci], stride AST
    int t = threadIdx.x, wid = t >> 5, lane = t & 31;
    int n = blockIdx.x >> 5;
    int pbase = (blockIdx.x & 31) << 7;

    // ---- prologue: A gather (strided over ci), W straight copy ----
    for (int idx = t; idx < 2048; idx += 256) {
        int r = idx & 127, ci0 = (idx >> 7) * 8;
        const float* src = in + ((size_t)n*CH + ci0)*HW + pbase + r;
        float4 u, v;
        u.x = src[0*HW]; u.y = src[1*HW]; u.z = src[2*HW]; u.w = src[3*HW];
        v.x = src[4*HW]; v.y = src[5*HW]; v.z = src[6*HW]; v.w = src[7*HW];
        *(float4*)&As[r*AST + ci0]     = u;
        *(float4*)&As[r*AST + ci0 + 4] = v;
    }
    for (int idx = t; idx < 4096; idx += 256) {
        int co = idx >> 5, q = idx & 31;
        *(float4*)&Ws[co*AST + q*4] = *(const float4*)(wt + co*CH + q*4);
    }
    __syncthreads();

    // ---- MMA: warp tile 64p x 32co, 16 K-steps of 8 ----
    int wm = wid & 1, wn = wid >> 1;
    int g = lane >> 2, tg = lane & 3;
    float d[4][4][4];
    #pragma unroll
    for (int mi = 0; mi < 4; mi++)
        #pragma unroll
        for (int ni = 0; ni < 4; ni++)
            #pragma unroll
            for (int r = 0; r < 4; r++) d[mi][ni][r] = 0.f;

    #pragma unroll
    for (int k = 0; k < 16; k++) {
        int c0 = k*8 + tg;
        unsigned a[4][4];
        #pragma unroll
        for (int mi = 0; mi < 4; mi++) {
            int row = (wm*64 + mi*16 + g) * AST;
            a[mi][0] = f2tf(As[row + c0]);
            a[mi][1] = f2tf(As[row + 8*AST + c0]);
            a[mi][2] = f2tf(As[row + c0 + 4]);
            a[mi][3] = f2tf(As[row + 8*AST + c0 + 4]);
        }
        unsigned b[4][2];
        #pragma unroll
        for (int ni = 0; ni < 4; ni++) {
            int row = (wn*32 + ni*8 + g) * AST;
            b[ni][0] = f2tf(Ws[row + c0]);
            b[ni][1] = f2tf(Ws[row + c0 + 4]);
        }
        #pragma unroll
        for (int mi = 0; mi < 4; mi++)
            #pragma unroll
            for (int ni = 0; ni < 4; ni++)
                mma_tf32(d[mi][ni], a[mi], b[ni]);
    }
    __syncthreads();

    // ---- stage D to smem as S[co][p] (stride AST), coalesced out + stats ----
    float* S = smem;   // 128*AST*4 = 67584 B
    #pragma unroll
    for (int mi = 0; mi < 4; mi++) {
        int p0 = wm*64 + mi*16 + g;
        #pragma unroll
        for (int ni = 0; ni < 4; ni++) {
            int co0 = wn*32 + ni*8 + tg*2;
            S[co0*AST + p0]          = d[mi][ni][0];
            S[(co0+1)*AST + p0]      = d[mi][ni][1];
            S[co0*AST + p0 + 8]      = d[mi][ni][2];
            S[(co0+1)*AST + p0 + 8]  = d[mi][ni][3];
        }
    }
    __syncthreads();
    {
        int co = t >> 1, p0 = (t & 1) * 64;
        const float4* src = (const float4*)(S + co*AST + p0);
        float4* dst = (float4*)(out + ((size_t)n*CH + co)*HW + pbase + p0);
        float s = 0.f, q = 0.f;
        #pragma unroll
        for (int i = 0; i < 16; i++) {
            float4 v = src[i];
            dst[i] = v;
            s += v.x + v.y + v.z + v.w;
            q += v.x*v.x + v.y*v.y + v.z*v.z + v.w*v.w;
        }
        atomicAdd(&g_sum[slot*CH + co], s);
        atomicAdd(&g_sq [slot*CH + co], q);
    }
}

// ---------------- final: weighted branch sum (+bn) and scatter ----------------
__global__ void k_final(const float* __restrict__ x, const float* __restrict__ wts,
                        float* __restrict__ out) {
    int n = blockIdx.x >> 7, c = blockIdx.x & 127;
    int win = g_winner[c];
    size_t ob = ((size_t)n*CH + c)*HW;
    float av = g_att[n*CH + c];
    const float4* xi = (const float4*)(x + ob);
    const float4* sg = (const float4*)(g_sig + n*HW);
    float4* o4 = (float4*)(out + ob);
    if (win < 0) {
        for (int i = threadIdx.x; i < HW/4; i += 256) {
            float4 v = xi[i], s = sg[i];
            v.x *= s.x*av; v.y *= s.y*av; v.z *= s.z*av; v.w *= s.w*av;
            o4[i] = v;
        }
        return;
    }
    int j = win;
    __shared__ float P[12];
    __shared__ float W[8];
    if (threadIdx.x < 8) W[threadIdx.x] = wts[threadIdx.x];
    if (threadIdx.x == 0) {
        const int slots[6] = {0,1,3,5,6,7};
        for (int q = 0; q < 6; q++) {
            float mean = g_sum[slots[q]*CH + j] / CNT;
            float var  = g_sq [slots[q]*CH + j] / CNT - mean*mean;
            P[q*2] = mean; P[q*2+1] = rsqrtf(var + EPS);
        }
    }
    __syncthreads();
    size_t jb = ((size_t)n*CH + j)*HW;
    const float4* p1 = (const float4*)(g_b1 + jb);
    const float4* p2 = (const float4*)(g_b2 + jb);
    const float4* p4 = (const float4*)(g_b4 + jb);
    const float4* p5 = (const float4*)(g_b5 + jb);
    const float4* p6 = (const float4*)(g_b6 + jb);
    const float4* p7 = (const float4*)(g_b7 + jb);
    for (int i = threadIdx.x; i < HW/4; i += 256) {
        float4 r, a;
        float4 xv = xi[i], s = sg[i];
        xv.x *= s.x*av; xv.y *= s.y*av; xv.z *= s.z*av; xv.w *= s.w*av;
        r.x = W[3]*xv.x; r.y = W[3]*xv.y; r.z = W[3]*xv.z; r.w = W[3]*xv.w;
        a = p1[i];
        r.x += W[1]*((a.x-P[0])*P[1]); r.y += W[1]*((a.y-P[0])*P[1]);
        r.z += W[1]*((a.z-P[0])*P[1]); r.w += W[1]*((a.w-P[0])*P[1]);
        a = p2[i];
        r.x += W[2]*((a.x-P[2])*P[3]); r.y += W[2]*((a.y-P[2])*P[3]);
        r.z += W[2]*((a.z-P[2])*P[3]); r.w += W[2]*((a.w-P[2])*P[3]);
        a = p4[i];
        r.x += W[4]*((a.x-P[4])*P[5]); r.y += W[4]*((a.y-P[4])*P[5]);
        r.z += W[4]*((a.z-P[4])*P[5]); r.w += W[4]*((a.w-P[4])*P[5]);
        a = p5[i];
        r.x += W[5]*((a.x-P[6])*P[7]); r.y += W[5]*((a.y-P[6])*P[7]);
        r.z += W[5]*((a.z-P[6])*P[7]); r.w += W[5]*((a.w-P[6])*P[7]);
        a = p6[i];
        r.x += W[6]*((a.x-P[8])*P[9]); r.y += W[6]*((a.y-P[8])*P[9]);
        r.z += W[6]*((a.z-P[8])*P[9]); r.w += W[6]*((a.w-P[8])*P[9]);
        a = p7[i];
        r.x += W[7]*((a.x-P[10])*P[11]); r.y += W[7]*((a.y-P[10])*P[11]);
        r.z += W[7]*((a.z-P[10])*P[11]); r.w += W[7]*((a.w-P[10])*P[11]);
        o4[i] = r;
    }
}

// ---------------- launch ----------------
extern "C" void kernel_launch(void* const* d_in, const int* in_sizes, int n_in,
                              void* d_out, int out_size) {
    const float* x    = (const float*)d_in[0];
    const float* wts  = (const float*)d_in[1];
    const float* fc1  = (const float*)d_in[2];
    const float* fc2  = (const float*)d_in[3];
    const float* saw  = (const float*)d_in[4];
    const float* s3d1 = (const float*)d_in[5];
    const float* s3p1 = (const float*)d_in[6];
    const float* s3d2 = (const float*)d_in[7];
    const float* s3p2 = (const float*)d_in[8];
    const float* s5d1 = (const float*)d_in[9];
    const float* s5p1 = (const float*)d_in[10];
    const float* s5d2 = (const float*)d_in[11];
    const float* s5p2 = (const float*)d_in[12];
    const float* d3d  = (const float*)d_in[13];
    const float* d3p  = (const float*)d_in[14];
    const float* d5d  = (const float*)d_in[15];
    const float* d5p  = (const float*)d_in[16];
    const int*   perm = (const int*)d_in[17];
    float* out = (float*)d_out;

    // Resolve real device addresses of __device__ globals (host shadow trap).
    float *p_bufA, *p_bufB, *p_b4, *p_b5, *p_b6, *p_b7;
    cudaGetSymbolAddress((void**)&p_bufA, g_bufA);
    cudaGetSymbolAddress((void**)&p_bufB, g_bufB);
    cudaGetSymbolAddress((void**)&p_b4,  g_b4);
    cudaGetSymbolAddress((void**)&p_b5,  g_b5);
    cudaGetSymbolAddress((void**)&p_b6,  g_b6);
    cudaGetSymbolAddress((void**)&p_b7,  g_b7);

    cudaFuncSetAttribute(k_pwm, cudaFuncAttributeMaxDynamicSharedMemorySize, PWM_SMEM);

    k_zero_stats<<<4, 256>>>();

    k_chanstat<<<(NB*HW)/256, 256>>>(x);
    k_saconv<<<NB*16, 256>>>(saw);
    k_x1red<<<NB*CH, 256>>>(x);
    k_att<<<NB, 128>>>(fc1, fc2);
    k_topk<<<1, 128>>>(perm);

    // fused: x2 on the fly + pool (stats 0/1) + all four first-stage dws
    k_stage1<<<NB*CH, 256>>>(x, s3d1, s5d1, d3d, d5d);

    const int PWG = NB * 32;   // 1024 blocks: (n, 128-pixel tile)
    // sep3
    k_pwm<<<PWG, 256, PWM_SMEM>>>(p_bufA, s3p1, p_b4, 2);
    k_dw2<3><<<NB*CH, 256>>>(p_b4, s3d2, p_bufA, 2);
    k_pwm<<<PWG, 256, PWM_SMEM>>>(p_bufA, s3p2, p_b4, 3);
    // sep5
    k_pwm<<<PWG, 256, PWM_SMEM>>>(p_bufB, s5p1, p_b5, 4);
    k_dw2<5><<<NB*CH, 256>>>(p_b5, s5d2, p_bufB, 4);
    k_pwm<<<PWG, 256, PWM_SMEM>>>(p_bufB, s5p2, p_b5, 5);
    // dil3 / dil5: in-place (block reads its tile fully before storing)
    k_pwm<<<PWG, 256, PWM_SMEM>>>(p_b6, d3p, p_b6, 6);
    k_pwm<<<PWG, 256, PWM_SMEM>>>(p_b7, d5p, p_b7, 7);

    k_final<<<NB*CH, 256>>>(x, wts, out);
}

// round 14
// speedup vs baseline: 1.0699x; 1.0699x over previous
#include <cuda_runtime.h>
#include <cuda_bf16.h>
#include <math.h>
#include <cstdint>

#define NB 32
#define CH 128
#define HW 4096           // 64*64
#define CNT 131072.0f     // NB*HW, bn population per channel
#define EPS 1e-5f
#define SP 72             // padded plane stride (PAD=4 halo each side)
#define PPN (SP*SP)       // 5184

// ---------------- scratch (device globals; no mallocs allowed) ----------------
__device__ float g_s  [NB*2*HW];      // channel mean/max planes
__device__ float g_sig[NB*HW];        // spatial-attention sigmoid map
__device__ float g_bufA[NB*CH*HW];    // sep3 dw / scratch
__device__ float g_bufB[NB*CH*HW];    // sep5 dw / scratch
__device__ float g_b1 [NB*CH*HW];     // maxpool branch
__device__ float g_b2 [NB*CH*HW];     // avgpool branch
__device__ float g_b4 [NB*CH*HW];     // sep3 branch
__device__ float g_b5 [NB*CH*HW];     // sep5 branch
__device__ float g_b6 [NB*CH*HW];     // dil3 branch
__device__ float g_b7 [NB*CH*HW];     // dil5 branch
__device__ float g_psum[NB*CH];
__device__ float g_pmax[NB*CH];
__device__ float g_att [NB*CH];
__device__ int   g_nd[CH];
__device__ int   g_winner[CH];
__device__ float g_sum[8*CH];         // bn stats slots
__device__ float g_sq [8*CH];

// ---------------- tiny helper kernels ----------------
__global__ void k_zero_stats() {
    int i = blockIdx.x*256 + threadIdx.x;
    if (i < 8*CH) { g_sum[i] = 0.f; g_sq[i] = 0.f; }
}

// ---------------- stage A: spatial attention ----------------
__global__ void k_chanstat(const float* __restrict__ x) {
    int idx = blockIdx.x*256 + threadIdx.x;       // n*HW + hw
    if (idx >= NB*HW) return;
    int n = idx >> 12, hw = idx & (HW-1);
    const float* p = x + (size_t)n*CH*HW + hw;
    float s = 0.f, m = -1e30f;
    #pragma unroll 8
    for (int c = 0; c < CH; c++) { float v = p[c*HW]; s += v; m = fmaxf(m, v); }
    g_s[n*2*HW + hw]      = s * (1.f/CH);
    g_s[n*2*HW + HW + hw] = m;
}

__global__ void k_saconv(const float* __restrict__ saw) {
    __shared__ float w[98];
    if (threadIdx.x < 98) w[threadIdx.x] = saw[threadIdx.x];
    __syncthreads();
    int n  = blockIdx.x >> 4;
    int hw = (blockIdx.x & 15) * 256 + threadIdx.x;
    int h = hw >> 6, wx = hw & 63;
    const float* sp = g_s + n*2*HW;
    float acc = 0.f;
    #pragma unroll
    for (int ic = 0; ic < 2; ic++)
        #pragma unroll
        for (int kh = 0; kh < 7; kh++) {
            int ih = h + kh - 3;
            if (ih < 0 || ih > 63) continue;
            #pragma unroll
            for (int kw = 0; kw < 7; kw++) {
                int iw = wx + kw - 3;
                if (iw >= 0 && iw <= 63)
                    acc += __ldg(&sp[ic*HW + ih*64 + iw]) * w[ic*49 + kh*7 + kw];
            }
        }
    g_sig[n*HW + hw] = 1.f / (1.f + __expf(-acc));
}

// stats of x1 = x*sig over HW per (n,c)  (x1 not materialized)
__global__ void k_x1red(const float* __restrict__ x) {
    int n = blockIdx.x >> 7, c = blockIdx.x & 127;
    size_t base = ((size_t)n*CH + c)*HW;
    const float4* sg = (const float4*)(g_sig + n*HW);
    const float4* xi = (const float4*)(x + base);
    float s = 0.f, m = -1e30f;
    for (int i = threadIdx.x; i < HW/4; i += 256) {
        float4 v = xi[i], g = sg[i];
        float a = v.x*g.x, b = v.y*g.y, cc = v.z*g.z, dd = v.w*g.w;
        s += (a+b) + (cc+dd);
        m = fmaxf(m, fmaxf(fmaxf(a,b), fmaxf(cc,dd)));
    }
    __shared__ float rs[256], rm[256];
    rs[threadIdx.x] = s; rm[threadIdx.x] = m; __syncthreads();
    for (int o = 128; o > 0; o >>= 1) {
        if (threadIdx.x < o) {
            rs[threadIdx.x] += rs[threadIdx.x + o];
            rm[threadIdx.x] = fmaxf(rm[threadIdx.x], rm[threadIdx.x + o]);
        }
        __syncthreads();
    }
    if (threadIdx.x == 0) { g_psum[n*CH+c] = rs[0]; g_pmax[n*CH+c] = rm[0]; }
}

__global__ void k_att(const float* __restrict__ fc1, const float* __restrict__ fc2) {
    int n = blockIdx.x, t = threadIdx.x;   // 128 threads
    __shared__ float m[CH], mx[CH], hm[64], hx[64];
    m[t]  = g_psum[n*CH+t] * (1.f/HW);
    mx[t] = g_pmax[n*CH+t];
    __syncthreads();
    if (t < 64) {
        float a = 0.f, b = 0.f;
        for (int c = 0; c < CH; c++) { float w = fc1[t*CH+c]; a += w*m[c]; b += w*mx[c]; }
        hm[t] = fmaxf(a, 0.f); hx[t] = fmaxf(b, 0.f);
    }
    __syncthreads();
    float a = 0.f, b = 0.f;
    for (int k = 0; k < 64; k++) { float w = fc2[t*64+k]; a += w*hm[k]; b += w*hx[k]; }
    g_att[n*CH+t] = 1.f / (1.f + __expf(-(a + b)));
}

__global__ void k_topk(const int* __restrict__ perm) {
    int c = threadIdx.x;   // 128 threads
    __shared__ float sl[CH];
    float s = 0.f;
    for (int n = 0; n < NB; n++) s += g_att[n*CH + c];
    sl[c] = s; __syncthreads();
    float v = sl[c];
    int rank = 0;
    for (int d = 0; d < CH; d++) { float u = sl[d]; rank += (u > v) || (u == v && d < c); }
    if (rank < 96) g_nd[rank] = c;
    if (c < 32) g_nd[96 + c] = perm[c];
    int win;
    if (c < 32) {
        int inv = 0;
        for (int i = 0; i < 32; i++) if (perm[i] == c) inv = i;
        win = 96 + inv;                 // perm positions are last -> always win
    } else {
        win = (rank < 96) ? rank : -1;
    }
    g_winner[c] = win;
}

// ---------------- depthwise quad helper ----------------
template<int KS, int DIL>
__device__ __forceinline__ void dw_quad(const float* __restrict__ pl, int h, int w0,
                                        const float* __restrict__ wt, float4* outv) {
    constexpr int R2 = (KS/2)*DIL;
    float a0 = 0.f, a1 = 0.f, a2 = 0.f, a3 = 0.f;
    #pragma unroll
    for (int kh = 0; kh < KS; kh++) {
        int ph = h + 4 + (kh - KS/2)*DIL;
        const float4* rp = (const float4*)&pl[ph*SP + w0];
        float buf[12];
        #pragma unroll
        for (int l = 0; l < 3; l++) {
            float4 t = rp[l];
            buf[l*4+0]=t.x; buf[l*4+1]=t.y; buf[l*4+2]=t.z; buf[l*4+3]=t.w;
        }
        #pragma unroll
        for (int kw = 0; kw < KS; kw++) {
            float wv = wt[kh*KS + kw];
            constexpr int base = 4 - R2;
            int b = base + kw*DIL;
            a0 += buf[b+0]*wv; a1 += buf[b+1]*wv; a2 += buf[b+2]*wv; a3 += buf[b+3]*wv;
        }
    }
    *outv = make_float4(a0, a1, a2, a3);
}

// ---------------- stage-1 fusion: x2 on-the-fly + pool + 4 first dws ----------
__global__ void __launch_bounds__(256) k_stage1(
        const float* __restrict__ x,
        const float* __restrict__ w3, const float* __restrict__ w5,
        const float* __restrict__ wd3, const float* __restrict__ wd5) {
    __shared__ float raw[HW];
    __shared__ float pp[PPN];
    __shared__ float red[1024];
    __shared__ float sw3[9], sw5[25], swd3[9], swd5[25];
    int n = blockIdx.x >> 7, j = blockIdx.x & 127;
    int t = threadIdx.x;
    int cin = g_nd[j];
    float av = g_att[n*CH + cin];
    if (t < 9)  sw3[t]  = w3[j*9 + t];
    if (t < 25) sw5[t]  = w5[j*25 + t];
    if (t >= 32 && t < 41)  swd3[t-32] = wd3[j*9 + (t-32)];
    if (t >= 64 && t < 89)  swd5[t-64] = wd5[j*25 + (t-64)];
    for (int i = t; i < PPN/4; i += 256) ((float4*)pp)[i] = make_float4(0,0,0,0);
    __syncthreads();
    const float4* in4 = (const float4*)(x + ((size_t)n*CH + cin)*HW);
    const float4* sg4 = (const float4*)(g_sig + n*HW);
    for (int q = t; q < 1024; q += 256) {
        float4 v = in4[q], s = sg4[q];
        v.x *= s.x*av; v.y *= s.y*av; v.z *= s.z*av; v.w *= s.w*av;
        ((float4*)raw)[q] = v;
        int h = q >> 4, c4 = (q & 15) * 4;
        float4 r = make_float4(fmaxf(v.x,0.f), fmaxf(v.y,0.f), fmaxf(v.z,0.f), fmaxf(v.w,0.f));
        *(float4*)&pp[(h+4)*SP + c4 + 4] = r;
    }
    __syncthreads();

    size_t ob = ((size_t)n*CH + j)*HW;
    float s1 = 0.f, q1 = 0.f, s2 = 0.f, q2 = 0.f;
    for (int i = t; i < HW; i += 256) {
        int h = i >> 6, w = i & 63;
        int h0 = max(h-1,0), h1 = min(h+1,63), w0 = max(w-1,0), w1 = min(w+1,63);
        float mx = -1e30f, sm = 0.f;
        for (int hh = h0; hh <= h1; hh++)
            for (int ww = w0; ww <= w1; ww++) {
                float v = raw[hh*64+ww];
                mx = fmaxf(mx, v); sm += v;
            }
        float avp = sm / (float)((h1-h0+1)*(w1-w0+1));
        g_b1[ob+i] = mx; g_b2[ob+i] = avp;
        s1 += mx; q1 += mx*mx; s2 += avp; q2 += avp*avp;
    }
    red[t] = s1; red[256+t] = q1; red[512+t] = s2; red[768+t] = q2;
    __syncthreads();
    for (int o = 128; o > 0; o >>= 1) {
        if (t < o) {
            red[t]     += red[t+o];
            red[256+t] += red[256+t+o];
            red[512+t] += red[512+t+o];
            red[768+t] += red[768+t+o];
        }
        __syncthreads();
    }
    if (t == 0) {
        atomicAdd(&g_sum[0*CH+j], red[0]);   atomicAdd(&g_sq[0*CH+j], red[256]);
        atomicAdd(&g_sum[1*CH+j], red[512]); atomicAdd(&g_sq[1*CH+j], red[768]);
    }
    for (int q = t; q < 1024; q += 256) {
        int h = q >> 4, w0 = (q & 15) * 4;
        float4 o4;
        dw_quad<3,1>(pp, h, w0, sw3,  &o4); *(float4*)&g_bufA[ob + h*64 + w0] = o4;
        dw_quad<5,1>(pp, h, w0, sw5,  &o4); *(float4*)&g_bufB[ob + h*64 + w0] = o4;
        dw_quad<3,2>(pp, h, w0, swd3, &o4); *(float4*)&g_b6 [ob + h*64 + w0] = o4;
        dw_quad<5,2>(pp, h, w0, swd5, &o4); *(float4*)&g_b7 [ob + h*64 + w0] = o4;
    }
}

// second-stage dw body: in -> bn(slot)+relu -> dw(KS, dil1) -> out
template<int KS>
__device__ __forceinline__ void dw2_body(const float* __restrict__ in,
                                         const float* __restrict__ dwW,
                                         float* __restrict__ out, int slot,
                                         int bid, float* pp, float* wt) {
    int n = bid >> 7, j = bid & 127;
    int t = threadIdx.x;
    if (t < KS*KS) wt[t] = dwW[j*KS*KS + t];
    float mean = g_sum[slot*CH + j] / CNT;
    float var  = g_sq [slot*CH + j] / CNT - mean*mean;
    float rstd = rsqrtf(var + EPS);
    for (int i = t; i < PPN/4; i += 256) ((float4*)pp)[i] = make_float4(0,0,0,0);
    __syncthreads();
    const float4* in4 = (const float4*)(in + ((size_t)n*CH + j)*HW);
    for (int q = t; q < 1024; q += 256) {
        float4 v = in4[q];
        int h = q >> 4, c4 = (q & 15) * 4;
        float4 r = make_float4(fmaxf((v.x-mean)*rstd, 0.f), fmaxf((v.y-mean)*rstd, 0.f),
                               fmaxf((v.z-mean)*rstd, 0.f), fmaxf((v.w-mean)*rstd, 0.f));
        *(float4*)&pp[(h+4)*SP + c4 + 4] = r;
    }
    __syncthreads();
    size_t ob = ((size_t)n*CH + j)*HW;
    for (int q = t; q < 1024; q += 256) {
        int h = q >> 4, w0 = (q & 15) * 4;
        float4 o4;
        dw_quad<KS,1>(pp, h, w0, wt, &o4);
        *(float4*)&out[ob + h*64 + w0] = o4;
    }
}

// merged dw2 launch: blocks [0,4096) -> sep3 (KS=3), [4096,8192) -> sep5 (KS=5)
__global__ void __launch_bounds__(256) k_dw2m(
        const float* __restrict__ inA, const float* __restrict__ wA,
        float* __restrict__ outA, int slotA,
        const float* __restrict__ inB, const float* __restrict__ wB,
        float* __restrict__ outB, int slotB) {
    __shared__ float pp[PPN];
    __shared__ float wt[25];
    if (blockIdx.x < NB*CH)
        dw2_body<3>(inA, wA, outA, slotA, blockIdx.x, pp, wt);
    else
        dw2_body<5>(inB, wB, outB, slotB, blockIdx.x - NB*CH, pp, wt);
}

// ---------------- tensor-core pointwise conv via mma.sync (bf16 split) ----------
// D[p,co] = sum_ci A[p,ci]*W[co,ci]; A=Ah+Al, W=Wh+Wl; D = AhWh + AhWl + AlWh.
// Block: one (n, 128-pixel tile). 8 warps = 2(m)x4(n), warp tile 64p x 32co.
#define AST 136                      // bf16 row stride (272 B)
#define TILE_B (128*AST*2)           // 34816 B per bf16 tile
#define PWM_AHI 0
#define PWM_ALO (PWM_AHI + TILE_B)
#define PWM_WHI (PWM_ALO + TILE_B)
#define PWM_WLO (PWM_WHI + TILE_B)
#define PWM_SMEM (PWM_WLO + TILE_B)  // 139264 B

__device__ __forceinline__ unsigned pk2(float a, float b, float* rla, float* rlb) {
    __nv_bfloat16 ha = __float2bfloat16(a), hb = __float2bfloat16(b);
    *rla = a - __bfloat162float(ha);
    *rlb = b - __bfloat162float(hb);
    __nv_bfloat162 v; v.x = ha; v.y = hb;
    return *(unsigned*)&v;
}
__device__ __forceinline__ unsigned pklo(float a, float b) {
    __nv_bfloat162 v; v.x = __float2bfloat16(a); v.y = __float2bfloat16(b);
    return *(unsigned*)&v;
}
__device__ __forceinline__ unsigned lds_u32(const char* base, int row, int col) {
    return *(const unsigned*)(base + row*(AST*2) + col*2);
}
__device__ __forceinline__ void mma_bf16(float* d, const unsigned* a, const unsigned* b) {
    asm volatile(
        "mma.sync.aligned.m16n8k16.row.col.f32.bf16.bf16.f32 "
        "{%0,%1,%2,%3}, {%4,%5,%6,%7}, {%8,%9}, {%0,%1,%2,%3};"
        : "+f"(d[0]), "+f"(d[1]), "+f"(d[2]), "+f"(d[3])
        : "r"(a[0]), "r"(a[1]), "r"(a[2]), "r"(a[3]), "r"(b[0]), "r"(b[1]));
}

__device__ __forceinline__ void pwm_body(const float* __restrict__ in,
                                         const float* __restrict__ wt,
                                         float* __restrict__ out, int slot,
                                         int bid, char* smem) {
    int t = threadIdx.x, wid = t >> 5, lane = t & 31;
    int n = bid >> 5;
    int pbase = (bid & 31) << 7;

    // ---- load & split-convert: A rows=pixels, W rows=co; cols=ci ----
    for (int idx = t; idx < 2048; idx += 256) {
        int r = idx & 127, ci0 = (idx >> 7) * 8;
        uint32_t off = r*(AST*2) + ci0*2;
        {   // A
            const float* src = in + ((size_t)n*CH + ci0)*HW + pbase + r;
            float la, lb; uint4 hi, lo;
            hi.x = pk2(src[0*HW], src[1*HW], &la, &lb); lo.x = pklo(la, lb);
            hi.y = pk2(src[2*HW], src[3*HW], &la, &lb); lo.y = pklo(la, lb);
            hi.z = pk2(src[4*HW], src[5*HW], &la, &lb); lo.z = pklo(la, lb);
            hi.w = pk2(src[6*HW], src[7*HW], &la, &lb); lo.w = pklo(la, lb);
            *(uint4*)(smem + PWM_AHI + off) = hi;
            *(uint4*)(smem + PWM_ALO + off) = lo;
        }
        {   // W (original [co][ci] layout)
            const float4 wa = *(const float4*)(wt + r*CH + ci0);
            const float4 wb = *(const float4*)(wt + r*CH + ci0 + 4);
            float la, lb; uint4 hi, lo;
            hi.x = pk2(wa.x, wa.y, &la, &lb); lo.x = pklo(la, lb);
            hi.y = pk2(wa.z, wa.w, &la, &lb); lo.y = pklo(la, lb);
            hi.z = pk2(wb.x, wb.y, &la, &lb); lo.z = pklo(la, lb);
            hi.w = pk2(wb.z, wb.w, &la, &lb); lo.w = pklo(la, lb);
            *(uint4*)(smem + PWM_WHI + off) = hi;
            *(uint4*)(smem + PWM_WLO + off) = lo;
        }
    }
    __syncthreads();

    // ---- MMA: warp tile 64p x 32co ----
    int wm = wid & 1, wn = wid >> 1;
    int g = lane >> 2, tg = lane & 3;
    float d[4][4][4];
    #pragma unroll
    for (int mi = 0; mi < 4; mi++)
        #pragma unroll
        for (int ni = 0; ni < 4; ni++)
            #pragma unroll
            for (int r = 0; r < 4; r++) d[mi][ni][r] = 0.f;

    const int chainA[3] = {PWM_AHI, PWM_AHI, PWM_ALO};
    const int chainW[3] = {PWM_WHI, PWM_WLO, PWM_WHI};
    #pragma unroll
    for (int ch = 0; ch < 3; ch++) {
        const char* pA = smem + chainA[ch];
        const char* pW = smem + chainW[ch];
        #pragma unroll
        for (int k = 0; k < 8; k++) {
            int c0 = k*16 + tg*2;
            unsigned a[4][4];
            #pragma unroll
            for (int mi = 0; mi < 4; mi++) {
                int row = wm*64 + mi*16 + g;
                a[mi][0] = lds_u32(pA, row,     c0);
                a[mi][1] = lds_u32(pA, row + 8, c0);
                a[mi][2] = lds_u32(pA, row,     c0 + 8);
                a[mi][3] = lds_u32(pA, row + 8, c0 + 8);
            }
            unsigned b[4][2];
            #pragma unroll
            for (int ni = 0; ni < 4; ni++) {
                int row = wn*32 + ni*8 + g;
                b[ni][0] = lds_u32(pW, row, c0);
                b[ni][1] = lds_u32(pW, row, c0 + 8);
            }
            #pragma unroll
            for (int mi = 0; mi < 4; mi++)
                #pragma unroll
                for (int ni = 0; ni < 4; ni++)
                    mma_bf16(d[mi][ni], a[mi], b[ni]);
        }
    }
    __syncthreads();

    // ---- stage D to smem as S[co][p] (stride 132 floats), coalesced out ----
    float* S = (float*)smem;
    #pragma unroll
    for (int mi = 0; mi < 4; mi++) {
        int p0 = wm*64 + mi*16 + g;
        #pragma unroll
        for (int ni = 0; ni < 4; ni++) {
            int co0 = wn*32 + ni*8 + tg*2;
            S[co0*132 + p0]          = d[mi][ni][0];
            S[(co0+1)*132 + p0]      = d[mi][ni][1];
            S[co0*132 + p0 + 8]      = d[mi][ni][2];
            S[(co0+1)*132 + p0 + 8]  = d[mi][ni][3];
        }
    }
    __syncthreads();
    {
        int co = t >> 1, p0 = (t & 1) * 64;
        const float4* src = (const float4*)(S + co*132 + p0);
        float4* dst = (float4*)(out + ((size_t)n*CH + co)*HW + pbase + p0);
        float s = 0.f, q = 0.f;
        #pragma unroll
        for (int i = 0; i < 16; i++) {
            float4 v = src[i];
            dst[i] = v;
            s += v.x + v.y + v.z + v.w;
            q += v.x*v.x + v.y*v.y + v.z*v.z + v.w*v.w;
        }
        atomicAdd(&g_sum[slot*CH + co], s);
        atomicAdd(&g_sq [slot*CH + co], q);
    }
}

// merged pw launch: up to 4 independent GEMMs, 1024 blocks each
__global__ void __launch_bounds__(256, 1)
k_pw4(const float* in0, const float* w0, float* o0, int s0,
      const float* in1, const float* w1, float* o1, int s1,
      const float* in2, const float* w2, float* o2, int s2,
      const float* in3, const float* w3, float* o3, int s3) {
    extern __shared__ char smem[];
    int br = blockIdx.x >> 10, bid = blockIdx.x & 1023;
    const float *in, *wt; float* out; int slot;
    switch (br) {
        case 0:  in = in0; wt = w0; out = o0; slot = s0; break;
        case 1:  in = in1; wt = w1; out = o1; slot = s1; break;
        case 2:  in = in2; wt = w2; out = o2; slot = s2; break;
        default: in = in3; wt = w3; out = o3; slot = s3; break;
    }
    pwm_body(in, wt, out, slot, bid, smem);
}

// ---------------- final: weighted branch sum (+bn) and scatter ----------------
__global__ void k_final(const float* __restrict__ x, const float* __restrict__ wts,
                        float* __restrict__ out) {
    int n = blockIdx.x >> 7, c = blockIdx.x & 127;
    int win = g_winner[c];
    size_t ob = ((size_t)n*CH + c)*HW;
    float av = g_att[n*CH + c];
    const float4* xi = (const float4*)(x + ob);
    const float4* sg = (const float4*)(g_sig + n*HW);
    float4* o4 = (float4*)(out + ob);
    if (win < 0) {
        for (int i = threadIdx.x; i < HW/4; i += 256) {
            float4 v = xi[i], s = sg[i];
            v.x *= s.x*av; v.y *= s.y*av; v.z *= s.z*av; v.w *= s.w*av;
            o4[i] = v;
        }
        return;
    }
    int j = win;
    __shared__ float P[12];
    __shared__ float W[8];
    if (threadIdx.x < 8) W[threadIdx.x] = wts[threadIdx.x];
    if (threadIdx.x == 0) {
        const int slots[6] = {0,1,3,5,6,7};
        for (int q = 0; q < 6; q++) {
            float mean = g_sum[slots[q]*CH + j] / CNT;
            float var  = g_sq [slots[q]*CH + j] / CNT - mean*mean;
            P[q*2] = mean; P[q*2+1] = rsqrtf(var + EPS);
        }
    }
    __syncthreads();
    size_t jb = ((size_t)n*CH + j)*HW;
    const float4* p1 = (const float4*)(g_b1 + jb);
    const float4* p2 = (const float4*)(g_b2 + jb);
    const float4* p4 = (const float4*)(g_b4 + jb);
    const float4* p5 = (const float4*)(g_b5 + jb);
    const float4* p6 = (const float4*)(g_b6 + jb);
    const float4* p7 = (const float4*)(g_b7 + jb);
    for (int i = threadIdx.x; i < HW/4; i += 256) {
        float4 r, a;
        float4 xv = xi[i], s = sg[i];
        xv.x *= s.x*av; xv.y *= s.y*av; xv.z *= s.z*av; xv.w *= s.w*av;
        r.x = W[3]*xv.x; r.y = W[3]*xv.y; r.z = W[3]*xv.z; r.w = W[3]*xv.w;
        a = p1[i];
        r.x += W[1]*((a.x-P[0])*P[1]); r.y += W[1]*((a.y-P[0])*P[1]);
        r.z += W[1]*((a.z-P[0])*P[1]); r.w += W[1]*((a.w-P[0])*P[1]);
        a = p2[i];
        r.x += W[2]*((a.x-P[2])*P[3]); r.y += W[2]*((a.y-P[2])*P[3]);
        r.z += W[2]*((a.z-P[2])*P[3]); r.w += W[2]*((a.w-P[2])*P[3]);
        a = p4[i];
        r.x += W[4]*((a.x-P[4])*P[5]); r.y += W[4]*((a.y-P[4])*P[5]);
        r.z += W[4]*((a.z-P[4])*P[5]); r.w += W[4]*((a.w-P[4])*P[5]);
        a = p5[i];
        r.x += W[5]*((a.x-P[6])*P[7]); r.y += W[5]*((a.y-P[6])*P[7]);
        r.z += W[5]*((a.z-P[6])*P[7]); r.w += W[5]*((a.w-P[6])*P[7]);
        a = p6[i];
        r.x += W[6]*((a.x-P[8])*P[9]); r.y += W[6]*((a.y-P[8])*P[9]);
        r.z += W[6]*((a.z-P[8])*P[9]); r.w += W[6]*((a.w-P[8])*P[9]);
        a = p7[i];
        r.x += W[7]*((a.x-P[10])*P[11]); r.y += W[7]*((a.y-P[10])*P[11]);
        r.z += W[7]*((a.z-P[10])*P[11]); r.w += W[7]*((a.w-P[10])*P[11]);
        o4[i] = r;
    }
}

// ---------------- launch ----------------
extern "C" void kernel_launch(void* const* d_in, const int* in_sizes, int n_in,
                              void* d_out, int out_size) {
    const float* x    = (const float*)d_in[0];
    const float* wts  = (const float*)d_in[1];
    const float* fc1  = (const float*)d_in[2];
    const float* fc2  = (const float*)d_in[3];
    const float* saw  = (const float*)d_in[4];
    const float* s3d1 = (const float*)d_in[5];
    const float* s3p1 = (const float*)d_in[6];
    const float* s3d2 = (const float*)d_in[7];
    const float* s3p2 = (const float*)d_in[8];
    const float* s5d1 = (const float*)d_in[9];
    const float* s5p1 = (const float*)d_in[10];
    const float* s5d2 = (const float*)d_in[11];
    const float* s5p2 = (const float*)d_in[12];
    const float* d3d  = (const float*)d_in[13];
    const float* d3p  = (const float*)d_in[14];
    const float* d5d  = (const float*)d_in[15];
    const float* d5p  = (const float*)d_in[16];
    const int*   perm = (const int*)d_in[17];
    float* out = (float*)d_out;

    // Resolve real device addresses of __device__ globals (host shadow trap).
    float *p_bufA, *p_bufB, *p_b4, *p_b5, *p_b6, *p_b7;
    cudaGetSymbolAddress((void**)&p_bufA, g_bufA);
    cudaGetSymbolAddress((void**)&p_bufB, g_bufB);
    cudaGetSymbolAddress((void**)&p_b4,  g_b4);
    cudaGetSymbolAddress((void**)&p_b5,  g_b5);
    cudaGetSymbolAddress((void**)&p_b6,  g_b6);
    cudaGetSymbolAddress((void**)&p_b7,  g_b7);

    cudaFuncSetAttribute(k_pw4, cudaFuncAttributeMaxDynamicSharedMemorySize, PWM_SMEM);

    k_zero_stats<<<4, 256>>>();

    k_chanstat<<<(NB*HW)/256, 256>>>(x);
    k_saconv<<<NB*16, 256>>>(saw);
    k_x1red<<<NB*CH, 256>>>(x);
    k_att<<<NB, 128>>>(fc1, fc2);
    k_topk<<<1, 128>>>(perm);

    // fused: x2 on the fly + pool (stats 0/1) + all four first-stage dws
    k_stage1<<<NB*CH, 256>>>(x, s3d1, s5d1, d3d, d5d);

    // merged pw wave 1: sep3-pw1, sep5-pw1, dil3-pw (in-place), dil5-pw (in-place)
    k_pw4<<<4*NB*32, 256, PWM_SMEM>>>(
        p_bufA, s3p1, p_b4, 2,
        p_bufB, s5p1, p_b5, 4,
        p_b6,   d3p,  p_b6, 6,
        p_b7,   d5p,  p_b7, 7);

    // merged dw2: sep3 (bn s2) + sep5 (bn s4)
    k_dw2m<<<2*NB*CH, 256>>>(p_b4, s3d2, p_bufA, 2,
                             p_b5, s5d2, p_bufB, 4);

    // merged pw wave 2: sep3-pw2, sep5-pw2
    k_pw4<<<2*NB*32, 256, PWM_SMEM>>>(
        p_bufA, s3p2, p_b4, 3,
        p_bufB, s5p2, p_b5, 5,
        (const float*)nullptr, (const float*)nullptr, (float*)nullptr, 0,
        (const float*)nullptr, (const float*)nullptr, (float*)nullptr, 0);

    k_final<<<NB*CH, 256>>>(x, wts, out);
}

// round 15
// speedup vs baseline: 1.0834x; 1.0126x over previous
#include <cuda_runtime.h>
#include <cuda_bf16.h>
#include <math.h>
#include <cstdint>

#define NB 32
#define CH 128
#define HW 4096           // 64*64
#define CNT 131072.0f     // NB*HW, bn population per channel
#define EPS 1e-5f
#define SP 72             // padded plane stride (PAD=4 halo each side)
#define PPN (SP*SP)       // 5184

// ---------------- scratch (device globals; no mallocs allowed) ----------------
__device__ float g_s  [NB*2*HW];      // channel mean/max planes
__device__ float g_sig[NB*HW];        // spatial-attention sigmoid map
__device__ float g_bufA[NB*CH*HW];    // sep3 dw / scratch
__device__ float g_bufB[NB*CH*HW];    // sep5 dw / scratch
__device__ float g_b4 [NB*CH*HW];     // sep3 branch
__device__ float g_b5 [NB*CH*HW];     // sep5 branch
__device__ float g_b6 [NB*CH*HW];     // dil3 branch
__device__ float g_b7 [NB*CH*HW];     // dil5 branch
__device__ float g_psum[NB*CH];
__device__ float g_pmax[NB*CH];
__device__ float g_att [NB*CH];
__device__ int   g_nd[CH];
__device__ int   g_winner[CH];
__device__ float g_sum[8*CH];         // bn stats slots
__device__ float g_sq [8*CH];

// ---------------- tiny helper kernels ----------------
__global__ void k_zero_stats() {
    int i = blockIdx.x*256 + threadIdx.x;
    if (i < 8*CH) { g_sum[i] = 0.f; g_sq[i] = 0.f; }
}

// ---------------- stage A: spatial attention ----------------
__global__ void k_chanstat(const float* __restrict__ x) {
    int idx = blockIdx.x*256 + threadIdx.x;       // n*HW + hw
    if (idx >= NB*HW) return;
    int n = idx >> 12, hw = idx & (HW-1);
    const float* p = x + (size_t)n*CH*HW + hw;
    float s = 0.f, m = -1e30f;
    #pragma unroll 8
    for (int c = 0; c < CH; c++) { float v = p[c*HW]; s += v; m = fmaxf(m, v); }
    g_s[n*2*HW + hw]      = s * (1.f/CH);
    g_s[n*2*HW + HW + hw] = m;
}

__global__ void k_saconv(const float* __restrict__ saw) {
    __shared__ float w[98];
    if (threadIdx.x < 98) w[threadIdx.x] = saw[threadIdx.x];
    __syncthreads();
    int n  = blockIdx.x >> 4;
    int hw = (blockIdx.x & 15) * 256 + threadIdx.x;
    int h = hw >> 6, wx = hw & 63;
    const float* sp = g_s + n*2*HW;
    float acc = 0.f;
    #pragma unroll
    for (int ic = 0; ic < 2; ic++)
        #pragma unroll
        for (int kh = 0; kh < 7; kh++) {
            int ih = h + kh - 3;
            if (ih < 0 || ih > 63) continue;
            #pragma unroll
            for (int kw = 0; kw < 7; kw++) {
                int iw = wx + kw - 3;
                if (iw >= 0 && iw <= 63)
                    acc += __ldg(&sp[ic*HW + ih*64 + iw]) * w[ic*49 + kh*7 + kw];
            }
        }
    g_sig[n*HW + hw] = 1.f / (1.f + __expf(-acc));
}

// stats of x1 = x*sig over HW per (n,c)
__global__ void k_x1red(const float* __restrict__ x) {
    int n = blockIdx.x >> 7, c = blockIdx.x & 127;
    size_t base = ((size_t)n*CH + c)*HW;
    const float4* sg = (const float4*)(g_sig + n*HW);
    const float4* xi = (const float4*)(x + base);
    float s = 0.f, m = -1e30f;
    for (int i = threadIdx.x; i < HW/4; i += 256) {
        float4 v = xi[i], g = sg[i];
        float a = v.x*g.x, b = v.y*g.y, cc = v.z*g.z, dd = v.w*g.w;
        s += (a+b) + (cc+dd);
        m = fmaxf(m, fmaxf(fmaxf(a,b), fmaxf(cc,dd)));
    }
    __shared__ float rs[256], rm[256];
    rs[threadIdx.x] = s; rm[threadIdx.x] = m; __syncthreads();
    for (int o = 128; o > 0; o >>= 1) {
        if (threadIdx.x < o) {
            rs[threadIdx.x] += rs[threadIdx.x + o];
            rm[threadIdx.x] = fmaxf(rm[threadIdx.x], rm[threadIdx.x + o]);
        }
        __syncthreads();
    }
    if (threadIdx.x == 0) { g_psum[n*CH+c] = rs[0]; g_pmax[n*CH+c] = rm[0]; }
}

__global__ void k_att(const float* __restrict__ fc1, const float* __restrict__ fc2) {
    int n = blockIdx.x, t = threadIdx.x;   // 128 threads
    __shared__ float m[CH], mx[CH], hm[64], hx[64];
    m[t]  = g_psum[n*CH+t] * (1.f/HW);
    mx[t] = g_pmax[n*CH+t];
    __syncthreads();
    if (t < 64) {
        float a = 0.f, b = 0.f;
        for (int c = 0; c < CH; c++) { float w = fc1[t*CH+c]; a += w*m[c]; b += w*mx[c]; }
        hm[t] = fmaxf(a, 0.f); hx[t] = fmaxf(b, 0.f);
    }
    __syncthreads();
    float a = 0.f, b = 0.f;
    for (int k = 0; k < 64; k++) { float w = fc2[t*64+k]; a += w*hm[k]; b += w*hx[k]; }
    g_att[n*CH+t] = 1.f / (1.f + __expf(-(a + b)));
}

__global__ void k_topk(const int* __restrict__ perm) {
    int c = threadIdx.x;   // 128 threads
    __shared__ float sl[CH];
    float s = 0.f;
    for (int n = 0; n < NB; n++) s += g_att[n*CH + c];
    sl[c] = s; __syncthreads();
    float v = sl[c];
    int rank = 0;
    for (int d = 0; d < CH; d++) { float u = sl[d]; rank += (u > v) || (u == v && d < c); }
    if (rank < 96) g_nd[rank] = c;
    if (c < 32) g_nd[96 + c] = perm[c];
    int win;
    if (c < 32) {
        int inv = 0;
        for (int i = 0; i < 32; i++) if (perm[i] == c) inv = i;
        win = 96 + inv;                 // perm positions are last -> always win
    } else {
        win = (rank < 96) ? rank : -1;
    }
    g_winner[c] = win;
}

// ---------------- depthwise quad helper ----------------
template<int KS, int DIL>
__device__ __forceinline__ void dw_quad(const float* __restrict__ pl, int h, int w0,
                                        const float* __restrict__ wt, float4* outv) {
    constexpr int R2 = (KS/2)*DIL;
    float a0 = 0.f, a1 = 0.f, a2 = 0.f, a3 = 0.f;
    #pragma unroll
    for (int kh = 0; kh < KS; kh++) {
        int ph = h + 4 + (kh - KS/2)*DIL;
        const float4* rp = (const float4*)&pl[ph*SP + w0];
        float buf[12];
        #pragma unroll
        for (int l = 0; l < 3; l++) {
            float4 t = rp[l];
            buf[l*4+0]=t.x; buf[l*4+1]=t.y; buf[l*4+2]=t.z; buf[l*4+3]=t.w;
        }
        #pragma unroll
        for (int kw = 0; kw < KS; kw++) {
            float wv = wt[kh*KS + kw];
            constexpr int base = 4 - R2;
            int b = base + kw*DIL;
            a0 += buf[b+0]*wv; a1 += buf[b+1]*wv; a2 += buf[b+2]*wv; a3 += buf[b+3]*wv;
        }
    }
    *outv = make_float4(a0, a1, a2, a3);
}

// ---------------- stage-1 fusion: x2 on-the-fly + pool stats + 4 first dws ------
__global__ void __launch_bounds__(256) k_stage1(
        const float* __restrict__ x,
        const float* __restrict__ w3, const float* __restrict__ w5,
        const float* __restrict__ wd3, const float* __restrict__ wd5) {
    __shared__ float raw[HW];
    __shared__ float pp[PPN];
    __shared__ float red[1024];
    __shared__ float sw3[9], sw5[25], swd3[9], swd5[25];
    int n = blockIdx.x >> 7, j = blockIdx.x & 127;
    int t = threadIdx.x;
    int cin = g_nd[j];
    float av = g_att[n*CH + cin];
    if (t < 9)  sw3[t]  = w3[j*9 + t];
    if (t < 25) sw5[t]  = w5[j*25 + t];
    if (t >= 32 && t < 41)  swd3[t-32] = wd3[j*9 + (t-32)];
    if (t >= 64 && t < 89)  swd5[t-64] = wd5[j*25 + (t-64)];
    for (int i = t; i < PPN/4; i += 256) ((float4*)pp)[i] = make_float4(0,0,0,0);
    __syncthreads();
    const float4* in4 = (const float4*)(x + ((size_t)n*CH + cin)*HW);
    const float4* sg4 = (const float4*)(g_sig + n*HW);
    for (int q = t; q < 1024; q += 256) {
        float4 v = in4[q], s = sg4[q];
        v.x *= s.x*av; v.y *= s.y*av; v.z *= s.z*av; v.w *= s.w*av;
        ((float4*)raw)[q] = v;
        int h = q >> 4, c4 = (q & 15) * 4;
        float4 r = make_float4(fmaxf(v.x,0.f), fmaxf(v.y,0.f), fmaxf(v.z,0.f), fmaxf(v.w,0.f));
        *(float4*)&pp[(h+4)*SP + c4 + 4] = r;
    }
    __syncthreads();

    size_t ob = ((size_t)n*CH + j)*HW;
    // pool stats only (branch values recomputed in k_final)
    float s1 = 0.f, q1 = 0.f, s2 = 0.f, q2 = 0.f;
    for (int i = t; i < HW; i += 256) {
        int h = i >> 6, w = i & 63;
        int h0 = max(h-1,0), h1 = min(h+1,63), w0 = max(w-1,0), w1 = min(w+1,63);
        float mx = -1e30f, sm = 0.f;
        for (int hh = h0; hh <= h1; hh++)
            for (int ww = w0; ww <= w1; ww++) {
                float v = raw[hh*64+ww];
                mx = fmaxf(mx, v); sm += v;
            }
        float avp = sm / (float)((h1-h0+1)*(w1-w0+1));
        s1 += mx; q1 += mx*mx; s2 += avp; q2 += avp*avp;
    }
    red[t] = s1; red[256+t] = q1; red[512+t] = s2; red[768+t] = q2;
    __syncthreads();
    for (int o = 128; o > 0; o >>= 1) {
        if (t < o) {
            red[t]     += red[t+o];
            red[256+t] += red[256+t+o];
            red[512+t] += red[512+t+o];
            red[768+t] += red[768+t+o];
        }
        __syncthreads();
    }
    if (t == 0) {
        atomicAdd(&g_sum[0*CH+j], red[0]);   atomicAdd(&g_sq[0*CH+j], red[256]);
        atomicAdd(&g_sum[1*CH+j], red[512]); atomicAdd(&g_sq[1*CH+j], red[768]);
    }
    for (int q = t; q < 1024; q += 256) {
        int h = q >> 4, w0 = (q & 15) * 4;
        float4 o4;
        dw_quad<3,1>(pp, h, w0, sw3,  &o4); *(float4*)&g_bufA[ob + h*64 + w0] = o4;
        dw_quad<5,1>(pp, h, w0, sw5,  &o4); *(float4*)&g_bufB[ob + h*64 + w0] = o4;
        dw_quad<3,2>(pp, h, w0, swd3, &o4); *(float4*)&g_b6 [ob + h*64 + w0] = o4;
        dw_quad<5,2>(pp, h, w0, swd5, &o4); *(float4*)&g_b7 [ob + h*64 + w0] = o4;
    }
}

// second-stage dw body: in -> bn(slot)+relu -> dw(KS, dil1) -> out
template<int KS>
__device__ __forceinline__ void dw2_body(const float* __restrict__ in,
                                         const float* __restrict__ dwW,
                                         float* __restrict__ out, int slot,
                                         int bid, float* pp, float* wt) {
    int n = bid >> 7, j = bid & 127;
    int t = threadIdx.x;
    if (t < KS*KS) wt[t] = dwW[j*KS*KS + t];
    float mean = g_sum[slot*CH + j] / CNT;
    float var  = g_sq [slot*CH + j] / CNT - mean*mean;
    float rstd = rsqrtf(var + EPS);
    for (int i = t; i < PPN/4; i += 256) ((float4*)pp)[i] = make_float4(0,0,0,0);
    __syncthreads();
    const float4* in4 = (const float4*)(in + ((size_t)n*CH + j)*HW);
    for (int q = t; q < 1024; q += 256) {
        float4 v = in4[q];
        int h = q >> 4, c4 = (q & 15) * 4;
        float4 r = make_float4(fmaxf((v.x-mean)*rstd, 0.f), fmaxf((v.y-mean)*rstd, 0.f),
                               fmaxf((v.z-mean)*rstd, 0.f), fmaxf((v.w-mean)*rstd, 0.f));
        *(float4*)&pp[(h+4)*SP + c4 + 4] = r;
    }
    __syncthreads();
    size_t ob = ((size_t)n*CH + j)*HW;
    for (int q = t; q < 1024; q += 256) {
        int h = q >> 4, w0 = (q & 15) * 4;
        float4 o4;
        dw_quad<KS,1>(pp, h, w0, wt, &o4);
        *(float4*)&out[ob + h*64 + w0] = o4;
    }
}

__global__ void __launch_bounds__(256) k_dw2m(
        const float* __restrict__ inA, const float* __restrict__ wA,
        float* __restrict__ outA, int slotA,
        const float* __restrict__ inB, const float* __restrict__ wB,
        float* __restrict__ outB, int slotB) {
    __shared__ float pp[PPN];
    __shared__ float wt[25];
    if (blockIdx.x < NB*CH)
        dw2_body<3>(inA, wA, outA, slotA, blockIdx.x, pp, wt);
    else
        dw2_body<5>(inB, wB, outB, slotB, blockIdx.x - NB*CH, pp, wt);
}

// ---------------- tensor-core pointwise conv via mma.sync (bf16 split) ----------
// D[p,co] = sum_ci A[p,ci]*W[co,ci]; A=Ah+Al, W=Wh+Wl; D = AhWh + AhWl + AlWh.
// Block: one (n, 128-pixel tile). 8 warps = 2(m)x4(n), warp tile 64p x 32co.
// Mainloop: fragments loaded ONCE per k-step via ldmatrix, 48 MMAs into shared accs.
#define AST 136                      // bf16 row stride (272 B)
#define TILE_B (128*AST*2)           // 34816 B per bf16 tile
#define PWM_AHI 0
#define PWM_ALO (PWM_AHI + TILE_B)
#define PWM_WHI (PWM_ALO + TILE_B)
#define PWM_WLO (PWM_WHI + TILE_B)
#define PWM_SMEM (PWM_WLO + TILE_B)  // 139264 B

__device__ __forceinline__ unsigned pk2(float a, float b, float* rla, float* rlb) {
    __nv_bfloat16 ha = __float2bfloat16(a), hb = __float2bfloat16(b);
    *rla = a - __bfloat162float(ha);
    *rlb = b - __bfloat162float(hb);
    __nv_bfloat162 v; v.x = ha; v.y = hb;
    return *(unsigned*)&v;
}
__device__ __forceinline__ unsigned pklo(float a, float b) {
    __nv_bfloat162 v; v.x = __float2bfloat16(a); v.y = __float2bfloat16(b);
    return *(unsigned*)&v;
}
__device__ __forceinline__ void ldsm_x4(unsigned* r, uint32_t addr) {
    asm volatile("ldmatrix.sync.aligned.m8n8.x4.shared.b16 {%0,%1,%2,%3}, [%4];"
        : "=r"(r[0]), "=r"(r[1]), "=r"(r[2]), "=r"(r[3]) : "r"(addr));
}
__device__ __forceinline__ void mma_bf16(float* d, const unsigned* a, const unsigned* b) {
    asm volatile(
        "mma.sync.aligned.m16n8k16.row.col.f32.bf16.bf16.f32 "
        "{%0,%1,%2,%3}, {%4,%5,%6,%7}, {%8,%9}, {%0,%1,%2,%3};"
        : "+f"(d[0]), "+f"(d[1]), "+f"(d[2]), "+f"(d[3])
        : "r"(a[0]), "r"(a[1]), "r"(a[2]), "r"(a[3]), "r"(b[0]), "r"(b[1]));
}

__device__ __forceinline__ void pwm_body(const float* __restrict__ in,
                                         const float* __restrict__ wt,
                                         float* __restrict__ out, int slot,
                                         int bid, char* smem) {
    int t = threadIdx.x, wid = t >> 5, lane = t & 31;
    int n = bid >> 5;
    int pbase = (bid & 31) << 7;

    // ---- load & split-convert: A rows=pixels, W rows=co; cols=ci ----
    for (int idx = t; idx < 2048; idx += 256) {
        int r = idx & 127, ci0 = (idx >> 7) * 8;
        uint32_t off = r*(AST*2) + ci0*2;
        {   // A
            const float* src = in + ((size_t)n*CH + ci0)*HW + pbase + r;
            float la, lb; uint4 hi, lo;
            hi.x = pk2(src[0*HW], src[1*HW], &la, &lb); lo.x = pklo(la, lb);
            hi.y = pk2(src[2*HW], src[3*HW], &la, &lb); lo.y = pklo(la, lb);
            hi.z = pk2(src[4*HW], src[5*HW], &la, &lb); lo.z = pklo(la, lb);
            hi.w = pk2(src[6*HW], src[7*HW], &la, &lb); lo.w = pklo(la, lb);
            *(uint4*)(smem + PWM_AHI + off) = hi;
            *(uint4*)(smem + PWM_ALO + off) = lo;
        }
        {   // W (original [co][ci] layout)
            const float4 wa = *(const float4*)(wt + r*CH + ci0);
            const float4 wb = *(const float4*)(wt + r*CH + ci0 + 4);
            float la, lb; uint4 hi, lo;
            hi.x = pk2(wa.x, wa.y, &la, &lb); lo.x = pklo(la, lb);
            hi.y = pk2(wa.z, wa.w, &la, &lb); lo.y = pklo(la, lb);
            hi.z = pk2(wb.x, wb.y, &la, &lb); lo.z = pklo(la, lb);
            hi.w = pk2(wb.z, wb.w, &la, &lb); lo.w = pklo(la, lb);
            *(uint4*)(smem + PWM_WHI + off) = hi;
            *(uint4*)(smem + PWM_WLO + off) = lo;
        }
    }
    __syncthreads();

    // ---- MMA: warp tile 64p x 32co, ldmatrix fragment loads ----
    int wm = wid & 1, wn = wid >> 1;
    int g = lane >> 2, tg = lane & 3;
    float d[4][4][4];
    #pragma unroll
    for (int mi = 0; mi < 4; mi++)
        #pragma unroll
        for (int ni = 0; ni < 4; ni++)
            #pragma unroll
            for (int r = 0; r < 4; r++) d[mi][ni][r] = 0.f;

    uint32_t sb = (uint32_t)__cvta_generic_to_shared(smem);
    // A x4 lane mapping: row = base + (lane&15), col byte = k*32 + (lane>>4)*16
    uint32_t aOff = (uint32_t)((wm*64 + (lane & 15)) * (AST*2) + (lane >> 4) * 16);
    // W x4 (2 ni per load): row = base + (lane&7) + ((lane>>4)<<3), col byte = k*32 + ((lane>>3)&1)*16
    uint32_t wOff = (uint32_t)((wn*32 + (lane & 7) + ((lane >> 4) << 3)) * (AST*2)
                               + ((lane >> 3) & 1) * 16);
    uint32_t aHi = sb + PWM_AHI + aOff, aLo = sb + PWM_ALO + aOff;
    uint32_t wHi = sb + PWM_WHI + wOff, wLo = sb + PWM_WLO + wOff;

    #pragma unroll
    for (int k = 0; k < 8; k++) {
        unsigned ah[4][4], al[4][4], bh[2][4], bl[2][4];
        uint32_t kb = k * 32;
        #pragma unroll
        for (int mi = 0; mi < 4; mi++) {
            ldsm_x4(ah[mi], aHi + mi*16*(AST*2) + kb);
            ldsm_x4(al[mi], aLo + mi*16*(AST*2) + kb);
        }
        #pragma unroll
        for (int p = 0; p < 2; p++) {
            ldsm_x4(bh[p], wHi + p*16*(AST*2) + kb);
            ldsm_x4(bl[p], wLo + p*16*(AST*2) + kb);
        }
        #pragma unroll
        for (int mi = 0; mi < 4; mi++)
            #pragma unroll
            for (int ni = 0; ni < 4; ni++) {
                const unsigned* bhp = &bh[ni >> 1][(ni & 1) * 2];
                const unsigned* blp = &bl[ni >> 1][(ni & 1) * 2];
                mma_bf16(d[mi][ni], ah[mi], bhp);
                mma_bf16(d[mi][ni], ah[mi], blp);
                mma_bf16(d[mi][ni], al[mi], bhp);
            }
    }
    __syncthreads();

    // ---- stage D to smem as S[co][p] (stride 132 floats), coalesced out ----
    float* S = (float*)smem;
    #pragma unroll
    for (int mi = 0; mi < 4; mi++) {
        int p0 = wm*64 + mi*16 + g;
        #pragma unroll
        for (int ni = 0; ni < 4; ni++) {
            int co0 = wn*32 + ni*8 + tg*2;
            S[co0*132 + p0]          = d[mi][ni][0];
            S[(co0+1)*132 + p0]      = d[mi][ni][1];
            S[co0*132 + p0 + 8]      = d[mi][ni][2];
            S[(co0+1)*132 + p0 + 8]  = d[mi][ni][3];
        }
    }
    __syncthreads();
    {
        int co = t >> 1, p0 = (t & 1) * 64;
        const float4* src = (const float4*)(S + co*132 + p0);
        float4* dst = (float4*)(out + ((size_t)n*CH + co)*HW + pbase + p0);
        float s = 0.f, q = 0.f;
        #pragma unroll
        for (int i = 0; i < 16; i++) {
            float4 v = src[i];
            dst[i] = v;
            s += v.x + v.y + v.z + v.w;
            q += v.x*v.x + v.y*v.y + v.z*v.z + v.w*v.w;
        }
        atomicAdd(&g_sum[slot*CH + co], s);
        atomicAdd(&g_sq [slot*CH + co], q);
    }
}

// merged pw launch: up to 4 independent GEMMs, 1024 blocks each
__global__ void __launch_bounds__(256, 1)
k_pw4(const float* in0, const float* w0, float* o0, int s0,
      const float* in1, const float* w1, float* o1, int s1,
      const float* in2, const float* w2, float* o2, int s2,
      const float* in3, const float* w3, float* o3, int s3) {
    extern __shared__ char smem[];
    int br = blockIdx.x >> 10, bid = blockIdx.x & 1023;
    const float *in, *wt; float* out; int slot;
    switch (br) {
        case 0:  in = in0; wt = w0; out = o0; slot = s0; break;
        case 1:  in = in1; wt = w1; out = o1; slot = s1; break;
        case 2:  in = in2; wt = w2; out = o2; slot = s2; break;
        default: in = in3; wt = w3; out = o3; slot = s3; break;
    }
    pwm_body(in, wt, out, slot, bid, smem);
}

// ---------------- final: pools recomputed + weighted branch sum + scatter ------
__global__ void __launch_bounds__(256) k_final(const float* __restrict__ x,
                                               const float* __restrict__ wts,
                                               float* __restrict__ out) {
    __shared__ float raw[HW];
    __shared__ float P[12];
    __shared__ float W[8];
    int n = blockIdx.x >> 7, c = blockIdx.x & 127;
    int win = g_winner[c];
    size_t ob = ((size_t)n*CH + c)*HW;
    float av = g_att[n*CH + c];
    const float4* xi = (const float4*)(x + ob);
    const float4* sg = (const float4*)(g_sig + n*HW);
    float4* o4 = (float4*)(out + ob);
    if (win < 0) {
        for (int i = threadIdx.x; i < HW/4; i += 256) {
            float4 v = xi[i], s = sg[i];
            v.x *= s.x*av; v.y *= s.y*av; v.z *= s.z*av; v.w *= s.w*av;
            o4[i] = v;
        }
        return;
    }
    int j = win;
    int cin = g_nd[j];
    float avj = g_att[n*CH + cin];
    if (threadIdx.x < 8) W[threadIdx.x] = wts[threadIdx.x];
    if (threadIdx.x == 0) {
        const int slots[6] = {0,1,3,5,6,7};
        for (int q = 0; q < 6; q++) {
            float mean = g_sum[slots[q]*CH + j] / CNT;
            float var  = g_sq [slots[q]*CH + j] / CNT - mean*mean;
            P[q*2] = mean; P[q*2+1] = rsqrtf(var + EPS);
        }
    }
    // gathered plane for pool recompute (same arithmetic as stage1 -> identical values)
    const float4* xj = (const float4*)(x + ((size_t)n*CH + cin)*HW);
    for (int q = threadIdx.x; q < 1024; q += 256) {
        float4 v = xj[q], s = sg[q];
        v.x *= s.x*avj; v.y *= s.y*avj; v.z *= s.z*avj; v.w *= s.w*avj;
        ((float4*)raw)[q] = v;
    }
    __syncthreads();
    size_t jb = ((size_t)n*CH + j)*HW;
    const float4* p4 = (const float4*)(g_b4 + jb);
    const float4* p5 = (const float4*)(g_b5 + jb);
    const float4* p6 = (const float4*)(g_b6 + jb);
    const float4* p7 = (const float4*)(g_b7 + jb);
    for (int i = threadIdx.x; i < HW/4; i += 256) {
        float4 r, a;
        float4 xv = xi[i], s = sg[i];
        xv.x *= s.x*av; xv.y *= s.y*av; xv.z *= s.z*av; xv.w *= s.w*av;
        r.x = W[3]*xv.x; r.y = W[3]*xv.y; r.z = W[3]*xv.z; r.w = W[3]*xv.w;
        // recompute max/avg pool for 4 pixels
        int h = (i*4) >> 6, wpx = (i*4) & 63;
        float mxv[4], avv[4];
        #pragma unroll
        for (int u = 0; u < 4; u++) {
            int w = wpx + u;
            int h0 = max(h-1,0), h1 = min(h+1,63), w0 = max(w-1,0), w1 = min(w+1,63);
            float mx = -1e30f, sm = 0.f;
            for (int hh = h0; hh <= h1; hh++)
                for (int ww = w0; ww <= w1; ww++) {
                    float v = raw[hh*64+ww];
                    mx = fmaxf(mx, v); sm += v;
                }
            mxv[u] = mx;
            avv[u] = sm / (float)((h1-h0+1)*(w1-w0+1));
        }
        r.x += W[1]*((mxv[0]-P[0])*P[1]) + W[2]*((avv[0]-P[2])*P[3]);
        r.y += W[1]*((mxv[1]-P[0])*P[1]) + W[2]*((avv[1]-P[2])*P[3]);
        r.z += W[1]*((mxv[2]-P[0])*P[1]) + W[2]*((avv[2]-P[2])*P[3]);
        r.w += W[1]*((mxv[3]-P[0])*P[1]) + W[2]*((avv[3]-P[2])*P[3]);
        a = p4[i];
        r.x += W[4]*((a.x-P[4])*P[5]); r.y += W[4]*((a.y-P[4])*P[5]);
        r.z += W[4]*((a.z-P[4])*P[5]); r.w += W[4]*((a.w-P[4])*P[5]);
        a = p5[i];
        r.x += W[5]*((a.x-P[6])*P[7]); r.y += W[5]*((a.y-P[6])*P[7]);
        r.z += W[5]*((a.z-P[6])*P[7]); r.w += W[5]*((a.w-P[6])*P[7]);
        a = p6[i];
        r.x += W[6]*((a.x-P[8])*P[9]); r.y += W[6]*((a.y-P[8])*P[9]);
        r.z += W[6]*((a.z-P[8])*P[9]); r.w += W[6]*((a.w-P[8])*P[9]);
        a = p7[i];
        r.x += W[7]*((a.x-P[10])*P[11]); r.y += W[7]*((a.y-P[10])*P[11]);
        r.z += W[7]*((a.z-P[10])*P[11]); r.w += W[7]*((a.w-P[10])*P[11]);
        o4[i] = r;
    }
}

// ---------------- launch ----------------
extern "C" void kernel_launch(void* const* d_in, const int* in_sizes, int n_in,
                              void* d_out, int out_size) {
    const float* x    = (const float*)d_in[0];
    const float* wts  = (const float*)d_in[1];
    const float* fc1  = (const float*)d_in[2];
    const float* fc2  = (const float*)d_in[3];
    const float* saw  = (const float*)d_in[4];
    const float* s3d1 = (const float*)d_in[5];
    const float* s3p1 = (const float*)d_in[6];
    const float* s3d2 = (const float*)d_in[7];
    const float* s3p2 = (const float*)d_in[8];
    const float* s5d1 = (const float*)d_in[9];
    const float* s5p1 = (const float*)d_in[10];
    const float* s5d2 = (const float*)d_in[11];
    const float* s5p2 = (const float*)d_in[12];
    const float* d3d  = (const float*)d_in[13];
    const float* d3p  = (const float*)d_in[14];
    const float* d5d  = (const float*)d_in[15];
    const float* d5p  = (const float*)d_in[16];
    const int*   perm = (const int*)d_in[17];
    float* out = (float*)d_out;

    // Resolve real device addresses of __device__ globals (host shadow trap).
    float *p_bufA, *p_bufB, *p_b4, *p_b5, *p_b6, *p_b7;
    cudaGetSymbolAddress((void**)&p_bufA, g_bufA);
    cudaGetSymbolAddress((void**)&p_bufB, g_bufB);
    cudaGetSymbolAddress((void**)&p_b4,  g_b4);
    cudaGetSymbolAddress((void**)&p_b5,  g_b5);
    cudaGetSymbolAddress((void**)&p_b6,  g_b6);
    cudaGetSymbolAddress((void**)&p_b7,  g_b7);

    cudaFuncSetAttribute(k_pw4, cudaFuncAttributeMaxDynamicSharedMemorySize, PWM_SMEM);

    k_zero_stats<<<4, 256>>>();

    k_chanstat<<<(NB*HW)/256, 256>>>(x);
    k_saconv<<<NB*16, 256>>>(saw);
    k_x1red<<<NB*CH, 256>>>(x);
    k_att<<<NB, 128>>>(fc1, fc2);
    k_topk<<<1, 128>>>(perm);

    // fused: x2 on the fly + pool stats + all four first-stage dws
    k_stage1<<<NB*CH, 256>>>(x, s3d1, s5d1, d3d, d5d);

    // merged pw wave 1: sep3-pw1, sep5-pw1, dil3-pw (in-place), dil5-pw (in-place)
    k_pw4<<<4*NB*32, 256, PWM_SMEM>>>(
        p_bufA, s3p1, p_b4, 2,
        p_bufB, s5p1, p_b5, 4,
        p_b6,   d3p,  p_b6, 6,
        p_b7,   d5p,  p_b7, 7);

    // merged dw2: sep3 (bn s2) + sep5 (bn s4)
    k_dw2m<<<2*NB*CH, 256>>>(p_b4, s3d2, p_bufA, 2,
                             p_b5, s5d2, p_bufB, 4);

    // merged pw wave 2: sep3-pw2, sep5-pw2
    k_pw4<<<2*NB*32, 256, PWM_SMEM>>>(
        p_bufA, s3p2, p_b4, 3,
        p_bufB, s5p2, p_b5, 5,
        (const float*)nullptr, (const float*)nullptr, (float*)nullptr, 0,
        (const float*)nullptr, (const float*)nullptr, (float*)nullptr, 0);

    k_final<<<NB*CH, 256>>>(x, wts, out);
}

// round 17
// speedup vs baseline: 1.1654x; 1.0756x over previous
#include <cuda_runtime.h>
#include <cuda_bf16.h>
#include <math.h>
#include <cstdint>

#define NB 32
#define CH 128
#define HW 4096           // 64*64
#define CNT 131072.0f     // NB*HW, bn population per channel
#define EPS 1e-5f
#define SP 72             // padded plane stride (PAD=4 halo each side)
#define PPN (SP*SP)       // 5184
#define AST 136           // bf16 tile row stride (272 B)

// ---------------- scratch (device globals; no mallocs allowed) ----------------
__device__ float g_s  [NB*2*HW];      // channel mean/max planes
__device__ float g_sig[NB*HW];        // spatial-attention sigmoid map
__device__ float g_bufA[NB*CH*HW];    // sep3 dw / scratch
__device__ float g_bufB[NB*CH*HW];    // sep5 dw / scratch
__device__ float g_b4 [NB*CH*HW];     // sep3 branch
__device__ float g_b5 [NB*CH*HW];     // sep5 branch
__device__ float g_b6 [NB*CH*HW];     // dil3 branch
__device__ float g_b7 [NB*CH*HW];     // dil5 branch
__device__ float g_psum[NB*CH];
__device__ float g_pmax[NB*CH];
__device__ float g_att [NB*CH];
__device__ int   g_nd[CH];
__device__ int   g_winner[CH];
__device__ float g_sum[8*CH];         // bn stats slots
__device__ float g_sq [8*CH];
__device__ unsigned short g_wh[6*CH*AST];  // pre-converted W hi tiles (padded)
__device__ unsigned short g_wl[6*CH*AST];  // pre-converted W lo tiles

// ---------------- helpers ----------------
__device__ __forceinline__ unsigned pk2(float a, float b, float* rla, float* rlb) {
    __nv_bfloat16 ha = __float2bfloat16(a), hb = __float2bfloat16(b);
    *rla = a - __bfloat162float(ha);
    *rlb = b - __bfloat162float(hb);
    __nv_bfloat162 v; v.x = ha; v.y = hb;
    return *(unsigned*)&v;
}
__device__ __forceinline__ unsigned pklo(float a, float b) {
    __nv_bfloat162 v; v.x = __float2bfloat16(a); v.y = __float2bfloat16(b);
    return *(unsigned*)&v;
}
__device__ __forceinline__ void ldsm_x4(unsigned* r, uint32_t addr) {
    asm volatile("ldmatrix.sync.aligned.m8n8.x4.shared.b16 {%0,%1,%2,%3}, [%4];"
        : "=r"(r[0]), "=r"(r[1]), "=r"(r[2]), "=r"(r[3]) : "r"(addr));
}
__device__ __forceinline__ void mma_bf16(float* d, const unsigned* a, const unsigned* b) {
    asm volatile(
        "mma.sync.aligned.m16n8k16.row.col.f32.bf16.bf16.f32 "
        "{%0,%1,%2,%3}, {%4,%5,%6,%7}, {%8,%9}, {%0,%1,%2,%3};"
        : "+f"(d[0]), "+f"(d[1]), "+f"(d[2]), "+f"(d[3])
        : "r"(a[0]), "r"(a[1]), "r"(a[2]), "r"(a[3]), "r"(b[0]), "r"(b[1]));
}

// ---------------- tiny helper kernels ----------------
__global__ void k_zero_stats() {
    int i = blockIdx.x*256 + threadIdx.x;
    if (i < 8*CH) { g_sum[i] = 0.f; g_sq[i] = 0.f; }
}

// pre-convert the 6 pw weights to padded bf16 hi/lo tiles
__global__ void k_prew(const float* w0, const float* w1, const float* w2,
                       const float* w3, const float* w4, const float* w5) {
    const float* ws[6] = {w0,w1,w2,w3,w4,w5};
    const float* w = ws[blockIdx.x];
    unsigned short* oh = g_wh + blockIdx.x*CH*AST;
    unsigned short* ol = g_wl + blockIdx.x*CH*AST;
    for (int idx = threadIdx.x; idx < 2048; idx += 256) {
        int r = idx & 127, ci0 = (idx >> 7) * 8;
        float4 wa = *(const float4*)(w + r*CH + ci0);
        float4 wb = *(const float4*)(w + r*CH + ci0 + 4);
        float la, lb; uint4 hi, lo;
        hi.x = pk2(wa.x, wa.y, &la, &lb); lo.x = pklo(la, lb);
        hi.y = pk2(wa.z, wa.w, &la, &lb); lo.y = pklo(la, lb);
        hi.z = pk2(wb.x, wb.y, &la, &lb); lo.z = pklo(la, lb);
        hi.w = pk2(wb.z, wb.w, &la, &lb); lo.w = pklo(la, lb);
        *(uint4*)(oh + r*AST + ci0) = hi;
        *(uint4*)(ol + r*AST + ci0) = lo;
    }
    uint4 z = make_uint4(0,0,0,0);
    for (int r = threadIdx.x; r < 128; r += 256) {
        *(uint4*)(oh + r*AST + 128) = z;
        *(uint4*)(ol + r*AST + 128) = z;
    }
}

// ---------------- stage A: spatial attention ----------------
__global__ void k_chanstat(const float* __restrict__ x) {
    int idx = blockIdx.x*256 + threadIdx.x;       // n*HW + hw
    if (idx >= NB*HW) return;
    int n = idx >> 12, hw = idx & (HW-1);
    const float* p = x + (size_t)n*CH*HW + hw;
    float s = 0.f, m = -1e30f;
    #pragma unroll 8
    for (int c = 0; c < CH; c++) { float v = p[c*HW]; s += v; m = fmaxf(m, v); }
    g_s[n*2*HW + hw]      = s * (1.f/CH);
    g_s[n*2*HW + HW + hw] = m;
}

__global__ void k_saconv(const float* __restrict__ saw) {
    __shared__ float w[98];
    if (threadIdx.x < 98) w[threadIdx.x] = saw[threadIdx.x];
    __syncthreads();
    int n  = blockIdx.x >> 4;
    int hw = (blockIdx.x & 15) * 256 + threadIdx.x;
    int h = hw >> 6, wx = hw & 63;
    const float* sp = g_s + n*2*HW;
    float acc = 0.f;
    #pragma unroll
    for (int ic = 0; ic < 2; ic++)
        #pragma unroll
        for (int kh = 0; kh < 7; kh++) {
            int ih = h + kh - 3;
            if (ih < 0 || ih > 63) continue;
            #pragma unroll
            for (int kw = 0; kw < 7; kw++) {
                int iw = wx + kw - 3;
                if (iw >= 0 && iw <= 63)
                    acc += __ldg(&sp[ic*HW + ih*64 + iw]) * w[ic*49 + kh*7 + kw];
            }
        }
    g_sig[n*HW + hw] = 1.f / (1.f + __expf(-acc));
}

// stats of x1 = x*sig over HW per (n,c)
__global__ void k_x1red(const float* __restrict__ x) {
    int n = blockIdx.x >> 7, c = blockIdx.x & 127;
    size_t base = ((size_t)n*CH + c)*HW;
    const float4* sg = (const float4*)(g_sig + n*HW);
    const float4* xi = (const float4*)(x + base);
    float s = 0.f, m = -1e30f;
    for (int i = threadIdx.x; i < HW/4; i += 256) {
        float4 v = xi[i], g = sg[i];
        float a = v.x*g.x, b = v.y*g.y, cc = v.z*g.z, dd = v.w*g.w;
        s += (a+b) + (cc+dd);
        m = fmaxf(m, fmaxf(fmaxf(a,b), fmaxf(cc,dd)));
    }
    __shared__ float rs[256], rm[256];
    rs[threadIdx.x] = s; rm[threadIdx.x] = m; __syncthreads();
    for (int o = 128; o > 0; o >>= 1) {
        if (threadIdx.x < o) {
            rs[threadIdx.x] += rs[threadIdx.x + o];
            rm[threadIdx.x] = fmaxf(rm[threadIdx.x], rm[threadIdx.x + o]);
        }
        __syncthreads();
    }
    if (threadIdx.x == 0) { g_psum[n*CH+c] = rs[0]; g_pmax[n*CH+c] = rm[0]; }
}

__global__ void k_att(const float* __restrict__ fc1, const float* __restrict__ fc2) {
    int n = blockIdx.x, t = threadIdx.x;   // 128 threads
    __shared__ float m[CH], mx[CH], hm[64], hx[64];
    m[t]  = g_psum[n*CH+t] * (1.f/HW);
    mx[t] = g_pmax[n*CH+t];
    __syncthreads();
    if (t < 64) {
        float a = 0.f, b = 0.f;
        for (int c = 0; c < CH; c++) { float w = fc1[t*CH+c]; a += w*m[c]; b += w*mx[c]; }
        hm[t] = fmaxf(a, 0.f); hx[t] = fmaxf(b, 0.f);
    }
    __syncthreads();
    float a = 0.f, b = 0.f;
    for (int k = 0; k < 64; k++) { float w = fc2[t*64+k]; a += w*hm[k]; b += w*hx[k]; }
    g_att[n*CH+t] = 1.f / (1.f + __expf(-(a + b)));
}

__global__ void k_topk(const int* __restrict__ perm) {
    int c = threadIdx.x;   // 128 threads
    __shared__ float sl[CH];
    float s = 0.f;
    for (int n = 0; n < NB; n++) s += g_att[n*CH + c];
    sl[c] = s; __syncthreads();
    float v = sl[c];
    int rank = 0;
    for (int d = 0; d < CH; d++) { float u = sl[d]; rank += (u > v) || (u == v && d < c); }
    if (rank < 96) g_nd[rank] = c;
    if (c < 32) g_nd[96 + c] = perm[c];
    int win;
    if (c < 32) {
        int inv = 0;
        for (int i = 0; i < 32; i++) if (perm[i] == c) inv = i;
        win = 96 + inv;                 // perm positions are last -> always win
    } else {
        win = (rank < 96) ? rank : -1;
    }
    g_winner[c] = win;
}

// ---------------- depthwise quad helper ----------------
template<int KS, int DIL>
__device__ __forceinline__ void dw_quad(const float* __restrict__ pl, int h, int w0,
                                        const float* __restrict__ wt, float4* outv) {
    constexpr int R2 = (KS/2)*DIL;
    float a0 = 0.f, a1 = 0.f, a2 = 0.f, a3 = 0.f;
    #pragma unroll
    for (int kh = 0; kh < KS; kh++) {
        int ph = h + 4 + (kh - KS/2)*DIL;
        const float4* rp = (const float4*)&pl[ph*SP + w0];
        float buf[12];
        #pragma unroll
        for (int l = 0; l < 3; l++) {
            float4 t = rp[l];
            buf[l*4+0]=t.x; buf[l*4+1]=t.y; buf[l*4+2]=t.z; buf[l*4+3]=t.w;
        }
        #pragma unroll
        for (int kw = 0; kw < KS; kw++) {
            float wv = wt[kh*KS + kw];
            constexpr int base = 4 - R2;
            int b = base + kw*DIL;
            a0 += buf[b+0]*wv; a1 += buf[b+1]*wv; a2 += buf[b+2]*wv; a3 += buf[b+3]*wv;
        }
    }
    *outv = make_float4(a0, a1, a2, a3);
}

// ---------------- stage-1 fusion: x2 on-the-fly + pool stats + 4 first dws ------
__global__ void __launch_bounds__(256) k_stage1(
        const float* __restrict__ x,
        const float* __restrict__ w3, const float* __restrict__ w5,
        const float* __restrict__ wd3, const float* __restrict__ wd5) {
    __shared__ float raw[HW];
    __shared__ float pp[PPN];
    __shared__ float red[1024];
    __shared__ float sw3[9], sw5[25], swd3[9], swd5[25];
    int n = blockIdx.x >> 7, j = blockIdx.x & 127;
    int t = threadIdx.x;
    int cin = g_nd[j];
    float av = g_att[n*CH + cin];
    if (t < 9)  sw3[t]  = w3[j*9 + t];
    if (t < 25) sw5[t]  = w5[j*25 + t];
    if (t >= 32 && t < 41)  swd3[t-32] = wd3[j*9 + (t-32)];
    if (t >= 64 && t < 89)  swd5[t-64] = wd5[j*25 + (t-64)];
    for (int i = t; i < PPN/4; i += 256) ((float4*)pp)[i] = make_float4(0,0,0,0);
    __syncthreads();
    const float4* in4 = (const float4*)(x + ((size_t)n*CH + cin)*HW);
    const float4* sg4 = (const float4*)(g_sig + n*HW);
    for (int q = t; q < 1024; q += 256) {
        float4 v = in4[q], s = sg4[q];
        v.x *= s.x*av; v.y *= s.y*av; v.z *= s.z*av; v.w *= s.w*av;
        ((float4*)raw)[q] = v;
        int h = q >> 4, c4 = (q & 15) * 4;
        float4 r = make_float4(fmaxf(v.x,0.f), fmaxf(v.y,0.f), fmaxf(v.z,0.f), fmaxf(v.w,0.f));
        *(float4*)&pp[(h+4)*SP + c4 + 4] = r;
    }
    __syncthreads();

    size_t ob = ((size_t)n*CH + j)*HW;
    float s1 = 0.f, q1 = 0.f, s2 = 0.f, q2 = 0.f;
    for (int i = t; i < HW; i += 256) {
        int h = i >> 6, w = i & 63;
        int h0 = max(h-1,0), h1 = min(h+1,63), w0 = max(w-1,0), w1 = min(w+1,63);
        float mx = -1e30f, sm = 0.f;
        for (int hh = h0; hh <= h1; hh++)
            for (int ww = w0; ww <= w1; ww++) {
                float v = raw[hh*64+ww];
                mx = fmaxf(mx, v); sm += v;
            }
        float avp = sm / (float)((h1-h0+1)*(w1-w0+1));
        s1 += mx; q1 += mx*mx; s2 += avp; q2 += avp*avp;
    }
    red[t] = s1; red[256+t] = q1; red[512+t] = s2; red[768+t] = q2;
    __syncthreads();
    for (int o = 128; o > 0; o >>= 1) {
        if (t < o) {
            red[t]     += red[t+o];
            red[256+t] += red[256+t+o];
            red[512+t] += red[512+t+o];
            red[768+t] += red[768+t+o];
        }
        __syncthreads();
    }
    if (t == 0) {
        atomicAdd(&g_sum[0*CH+j], red[0]);   atomicAdd(&g_sq[0*CH+j], red[256]);
        atomicAdd(&g_sum[1*CH+j], red[512]); atomicAdd(&g_sq[1*CH+j], red[768]);
    }
    for (int q = t; q < 1024; q += 256) {
        int h = q >> 4, w0 = (q & 15) * 4;
        float4 o4;
        dw_quad<3,1>(pp, h, w0, sw3,  &o4); *(float4*)&g_bufA[ob + h*64 + w0] = o4;
        dw_quad<5,1>(pp, h, w0, sw5,  &o4); *(float4*)&g_bufB[ob + h*64 + w0] = o4;
        dw_quad<3,2>(pp, h, w0, swd3, &o4); *(float4*)&g_b6 [ob + h*64 + w0] = o4;
        dw_quad<5,2>(pp, h, w0, swd5, &o4); *(float4*)&g_b7 [ob + h*64 + w0] = o4;
    }
}

// second-stage dw body: in -> bn(slot)+relu -> dw(KS, dil1) -> out
template<int KS>
__device__ __forceinline__ void dw2_body(const float* __restrict__ in,
                                         const float* __restrict__ dwW,
                                         float* __restrict__ out, int slot,
                                         int bid, float* pp, float* wt) {
    int n = bid >> 7, j = bid & 127;
    int t = threadIdx.x;
    if (t < KS*KS) wt[t] = dwW[j*KS*KS + t];
    float mean = g_sum[slot*CH + j] / CNT;
    float var  = g_sq [slot*CH + j] / CNT - mean*mean;
    float rstd = rsqrtf(var + EPS);
    for (int i = t; i < PPN/4; i += 256) ((float4*)pp)[i] = make_float4(0,0,0,0);
    __syncthreads();
    const float4* in4 = (const float4*)(in + ((size_t)n*CH + j)*HW);
    for (int q = t; q < 1024; q += 256) {
        float4 v = in4[q];
        int h = q >> 4, c4 = (q & 15) * 4;
        float4 r = make_float4(fmaxf((v.x-mean)*rstd, 0.f), fmaxf((v.y-mean)*rstd, 0.f),
                               fmaxf((v.z-mean)*rstd, 0.f), fmaxf((v.w-mean)*rstd, 0.f));
        *(float4*)&pp[(h+4)*SP + c4 + 4] = r;
    }
    __syncthreads();
    size_t ob = ((size_t)n*CH + j)*HW;
    for (int q = t; q < 1024; q += 256) {
        int h = q >> 4, w0 = (q & 15) * 4;
        float4 o4;
        dw_quad<KS,1>(pp, h, w0, wt, &o4);
        *(float4*)&out[ob + h*64 + w0] = o4;
    }
}

__global__ void __launch_bounds__(256) k_dw2m(
        const float* __restrict__ inA, const float* __restrict__ wA,
        float* __restrict__ outA, int slotA,
        const float* __restrict__ inB, const float* __restrict__ wB,
        float* __restrict__ outB, int slotB) {
    __shared__ float pp[PPN];
    __shared__ float wt[25];
    if (blockIdx.x < NB*CH)
        dw2_body<3>(inA, wA, outA, slotA, blockIdx.x, pp, wt);
    else
        dw2_body<5>(inB, wB, outB, slotB, blockIdx.x - NB*CH, pp, wt);
}

// ---------------- tensor-core pointwise conv via mma.sync (bf16 split) ----------
// Block: one (n, 64-pixel tile), 2 blocks/SM. 8 warps = 2(m)x4(n), warp 32p x 32co.
#define TILE_A (64*AST*2)            // 17408 B
#define TILE_W (128*AST*2)           // 34816 B
#define PWM_AHI 0
#define PWM_ALO (PWM_AHI + TILE_A)
#define PWM_WHI (PWM_ALO + TILE_A)
#define PWM_WLO (PWM_WHI + TILE_W)
#define PWM_SMEM (PWM_WLO + TILE_W)  // 104448 B -> 2 blocks/SM
#define SST 68                       // fp32 epilogue staging stride

__device__ __forceinline__ void pwm_body(const float* __restrict__ in,
                                         int widx,
                                         float* __restrict__ out, int slot,
                                         int bid, char* smem) {
    int t = threadIdx.x, wid = t >> 5, lane = t & 31;
    int n = bid >> 6;
    int pbase = (bid & 63) << 6;

    // ---- prologue: A split-convert (64 rows x 16 ci-groups), W bf16 copies ----
    for (int idx = t; idx < 1024; idx += 256) {
        int r = idx & 63, ci0 = (idx >> 6) * 8;
        uint32_t off = r*(AST*2) + ci0*2;
        const float* src = in + ((size_t)n*CH + ci0)*HW + pbase + r;
        float la, lb; uint4 hi, lo;
        hi.x = pk2(src[0*HW], src[1*HW], &la, &lb); lo.x = pklo(la, lb);
        hi.y = pk2(src[2*HW], src[3*HW], &la, &lb); lo.y = pklo(la, lb);
        hi.z = pk2(src[4*HW], src[5*HW], &la, &lb); lo.z = pklo(la, lb);
        hi.w = pk2(src[6*HW], src[7*HW], &la, &lb); lo.w = pklo(la, lb);
        *(uint4*)(smem + PWM_AHI + off) = hi;
        *(uint4*)(smem + PWM_ALO + off) = lo;
    }
    {
        const uint4* wh4 = (const uint4*)(g_wh + widx*CH*AST);
        const uint4* wl4 = (const uint4*)(g_wl + widx*CH*AST);
        uint4* sWh = (uint4*)(smem + PWM_WHI);
        uint4* sWl = (uint4*)(smem + PWM_WLO);
        for (int i = t; i < TILE_W/16; i += 256) { sWh[i] = wh4[i]; sWl[i] = wl4[i]; }
    }
    __syncthreads();

    // ---- MMA: warp tile 32p x 32co ----
    int wm = wid & 1, wn = wid >> 1;
    int g = lane >> 2, tg = lane & 3;
    float d[2][4][4];
    #pragma unroll
    for (int mi = 0; mi < 2; mi++)
        #pragma unroll
        for (int ni = 0; ni < 4; ni++)
            #pragma unroll
            for (int r = 0; r < 4; r++) d[mi][ni][r] = 0.f;

    uint32_t sb = (uint32_t)__cvta_generic_to_shared(smem);
    uint32_t aOff = (uint32_t)((wm*32 + (lane & 15)) * (AST*2) + (lane >> 4) * 16);
    uint32_t wOff = (uint32_t)((wn*32 + (lane & 7) + ((lane >> 4) << 3)) * (AST*2)
                               + ((lane >> 3) & 1) * 16);
    uint32_t aHi = sb + PWM_AHI + aOff, aLo = sb + PWM_ALO + aOff;
    uint32_t wHi = sb + PWM_WHI + wOff, wLo = sb + PWM_WLO + wOff;

    #pragma unroll
    for (int k = 0; k < 8; k++) {
        unsigned ah[2][4], al[2][4], bh[2][4], bl[2][4];
        uint32_t kb = k * 32;
        #pragma unroll
        for (int mi = 0; mi < 2; mi++) {
            ldsm_x4(ah[mi], aHi + mi*16*(AST*2) + kb);
            ldsm_x4(al[mi], aLo + mi*16*(AST*2) + kb);
        }
        #pragma unroll
        for (int p = 0; p < 2; p++) {
            ldsm_x4(bh[p], wHi + p*16*(AST*2) + kb);
            ldsm_x4(bl[p], wLo + p*16*(AST*2) + kb);
        }
        #pragma unroll
        for (int mi = 0; mi < 2; mi++)
            #pragma unroll
            for (int ni = 0; ni < 4; ni++) {
                const unsigned* bhp = &bh[ni >> 1][(ni & 1) * 2];
                const unsigned* blp = &bl[ni >> 1][(ni & 1) * 2];
                mma_bf16(d[mi][ni], ah[mi], bhp);
                mma_bf16(d[mi][ni], ah[mi], blp);
                mma_bf16(d[mi][ni], al[mi], bhp);
            }
    }
    __syncthreads();

    // ---- stage D to smem as S[co][p] (stride SST), coalesced out + stats ----
    float* S = (float*)smem;   // 128*SST*4 = 34816 B
    #pragma unroll
    for (int mi = 0; mi < 2; mi++) {
        int p0 = wm*32 + mi*16 + g;
        #pragma unroll
        for (int ni = 0; ni < 4; ni++) {
            int co0 = wn*32 + ni*8 + tg*2;
            S[co0*SST + p0]          = d[mi][ni][0];
            S[(co0+1)*SST + p0]      = d[mi][ni][1];
            S[co0*SST + p0 + 8]      = d[mi][ni][2];
            S[(co0+1)*SST + p0 + 8]  = d[mi][ni][3];
        }
    }
    __syncthreads();
    {
        int co = t >> 1, p0 = (t & 1) * 32;
        const float4* src = (const float4*)(S + co*SST + p0);
        float4* dst = (float4*)(out + ((size_t)n*CH + co)*HW + pbase + p0);
        float s = 0.f, q = 0.f;
        #pragma unroll
        for (int i = 0; i < 8; i++) {
            float4 v = src[i];
            dst[i] = v;
            s += v.x + v.y + v.z + v.w;
            q += v.x*v.x + v.y*v.y + v.z*v.z + v.w*v.w;
        }
        s += __shfl_down_sync(0xffffffffu, s, 1);
        q += __shfl_down_sync(0xffffffffu, q, 1);
        if ((t & 1) == 0) {
            atomicAdd(&g_sum[slot*CH + co], s);
            atomicAdd(&g_sq [slot*CH + co], q);
        }
    }
}

// merged pw launch: up to 4 independent GEMMs, 2048 blocks each
__global__ void __launch_bounds__(256, 2)
k_pw4(const float* in0, int w0, float* o0, int s0,
      const float* in1, int w1, float* o1, int s1,
      const float* in2, int w2, float* o2, int s2,
      const float* in3, int w3, float* o3, int s3) {
    extern __shared__ char smem[];
    int br = blockIdx.x >> 11, bid = blockIdx.x & 2047;
    const float* in; int widx; float* out; int slot;
    switch (br) {
        case 0:  in = in0; widx = w0; out = o0; slot = s0; break;
        case 1:  in = in1; widx = w1; out = o1; slot = s1; break;
        case 2:  in = in2; widx = w2; out = o2; slot = s2; break;
        default: in = in3; widx = w3; out = o3; slot = s3; break;
    }
    pwm_body(in, widx, out, slot, bid, smem);
}

// ---------------- final: pools recomputed + weighted branch sum + scatter ------
__global__ void __launch_bounds__(256) k_final(const float* __restrict__ x,
                                               const float* __restrict__ wts,
                                               float* __restrict__ out) {
    __shared__ float raw[HW];
    __shared__ float P[12];
    __shared__ float W[8];
    int n = blockIdx.x >> 7, c = blockIdx.x & 127;
    int win = g_winner[c];
    size_t ob = ((size_t)n*CH + c)*HW;
    float av = g_att[n*CH + c];
    const float4* xi = (const float4*)(x + ob);
    const float4* sg = (const float4*)(g_sig + n*HW);
    float4* o4 = (float4*)(out + ob);
    if (win < 0) {
        for (int i = threadIdx.x; i < HW/4; i += 256) {
            float4 v = xi[i], s = sg[i];
            v.x *= s.x*av; v.y *= s.y*av; v.z *= s.z*av; v.w *= s.w*av;
            o4[i] = v;
        }
        return;
    }
    int j = win;
    int cin = g_nd[j];
    float avj = g_att[n*CH + cin];
    if (threadIdx.x < 8) W[threadIdx.x] = wts[threadIdx.x];
    if (threadIdx.x == 0) {
        const int slots[6] = {0,1,3,5,6,7};
        for (int q = 0; q < 6; q++) {
            float mean = g_sum[slots[q]*CH + j] / CNT;
            float var  = g_sq [slots[q]*CH + j] / CNT - mean*mean;
            P[q*2] = mean; P[q*2+1] = rsqrtf(var + EPS);
        }
    }
    const float4* xj = (const float4*)(x + ((size_t)n*CH + cin)*HW);
    for (int q = threadIdx.x; q < 1024; q += 256) {
        float4 v = xj[q], s = sg[q];
        v.x *= s.x*avj; v.y *= s.y*avj; v.z *= s.z*avj; v.w *= s.w*avj;
        ((float4*)raw)[q] = v;
    }
    __syncthreads();
    size_t jb = ((size_t)n*CH + j)*HW;
    const float4* p4 = (const float4*)(g_b4 + jb);
    const float4* p5 = (const float4*)(g_b5 + jb);
    const float4* p6 = (const float4*)(g_b6 + jb);
    const float4* p7 = (const float4*)(g_b7 + jb);
    for (int i = threadIdx.x; i < HW/4; i += 256) {
        float4 r, a;
        float4 xv = xi[i], s = sg[i];
        xv.x *= s.x*av; xv.y *= s.y*av; xv.z *= s.z*av; xv.w *= s.w*av;
        r.x = W[3]*xv.x; r.y = W[3]*xv.y; r.z = W[3]*xv.z; r.w = W[3]*xv.w;
        int h = (i*4) >> 6, wpx = (i*4) & 63;
        float mxv[4], avv[4];
        #pragma unroll
        for (int u = 0; u < 4; u++) {
            int w = wpx + u;
            int h0 = max(h-1,0), h1 = min(h+1,63), w0 = max(w-1,0), w1 = min(w+1,63);
            float mx = -1e30f, sm = 0.f;
            for (int hh = h0; hh <= h1; hh++)
                for (int ww = w0; ww <= w1; ww++) {
                    float v = raw[hh*64+ww];
                    mx = fmaxf(mx, v); sm += v;
                }
            mxv[u] = mx;
            avv[u] = sm / (float)((h1-h0+1)*(w1-w0+1));
        }
        r.x += W[1]*((mxv[0]-P[0])*P[1]) + W[2]*((avv[0]-P[2])*P[3]);
        r.y += W[1]*((mxv[1]-P[0])*P[1]) + W[2]*((avv[1]-P[2])*P[3]);
        r.z += W[1]*((mxv[2]-P[0])*P[1]) + W[2]*((avv[2]-P[2])*P[3]);
        r.w += W[1]*((mxv[3]-P[0])*P[1]) + W[2]*((avv[3]-P[2])*P[3]);
        a = p4[i];
        r.x += W[4]*((a.x-P[4])*P[5]); r.y += W[4]*((a.y-P[4])*P[5]);
        r.z += W[4]*((a.z-P[4])*P[5]); r.w += W[4]*((a.w-P[4])*P[5]);
        a = p5[i];
        r.x += W[5]*((a.x-P[6])*P[7]); r.y += W[5]*((a.y-P[6])*P[7]);
        r.z += W[5]*((a.z-P[6])*P[7]); r.w += W[5]*((a.w-P[6])*P[7]);
        a = p6[i];
        r.x += W[6]*((a.x-P[8])*P[9]); r.y += W[6]*((a.y-P[8])*P[9]);
        r.z += W[6]*((a.z-P[8])*P[9]); r.w += W[6]*((a.w-P[8])*P[9]);
        a = p7[i];
        r.x += W[7]*((a.x-P[10])*P[11]); r.y += W[7]*((a.y-P[10])*P[11]);
        r.z += W[7]*((a.z-P[10])*P[11]); r.w += W[7]*((a.w-P[10])*P[11]);
        o4[i] = r;
    }
}

// ---------------- launch ----------------
extern "C" void kernel_launch(void* const* d_in, const int* in_sizes, int n_in,
                              void* d_out, int out_size) {
    const float* x    = (const float*)d_in[0];
    const float* wts  = (const float*)d_in[1];
    const float* fc1  = (const float*)d_in[2];
    const float* fc2  = (const float*)d_in[3];
    const float* saw  = (const float*)d_in[4];
    const float* s3d1 = (const float*)d_in[5];
    const float* s3p1 = (const float*)d_in[6];
    const float* s3d2 = (const float*)d_in[7];
    const float* s3p2 = (const float*)d_in[8];
    const float* s5d1 = (const float*)d_in[9];
    const float* s5p1 = (const float*)d_in[10];
    const float* s5d2 = (const float*)d_in[11];
    const float* s5p2 = (const float*)d_in[12];
    const float* d3d  = (const float*)d_in[13];
    const float* d3p  = (const float*)d_in[14];
    const float* d5d  = (const float*)d_in[15];
    const float* d5p  = (const float*)d_in[16];
    const int*   perm = (const int*)d_in[17];
    float* out = (float*)d_out;

    // Resolve real device addresses of __device__ globals (host shadow trap).
    float *p_bufA, *p_bufB, *p_b4, *p_b5, *p_b6, *p_b7;
    cudaGetSymbolAddress((void**)&p_bufA, g_bufA);
    cudaGetSymbolAddress((void**)&p_bufB, g_bufB);
    cudaGetSymbolAddress((void**)&p_b4,  g_b4);
    cudaGetSymbolAddress((void**)&p_b5,  g_b5);
    cudaGetSymbolAddress((void**)&p_b6,  g_b6);
    cudaGetSymbolAddress((void**)&p_b7,  g_b7);

    cudaFuncSetAttribute(k_pw4, cudaFuncAttributeMaxDynamicSharedMemorySize, PWM_SMEM);

    k_zero_stats<<<4, 256>>>();
    k_prew<<<6, 256>>>(s3p1, s3p2, s5p1, s5p2, d3p, d5p);

    k_chanstat<<<(NB*HW)/256, 256>>>(x);
    k_saconv<<<NB*16, 256>>>(saw);
    k_x1red<<<NB*CH, 256>>>(x);
    k_att<<<NB, 128>>>(fc1, fc2);
    k_topk<<<1, 128>>>(perm);

    // fused: x2 on the fly + pool stats + all four first-stage dws
    k_stage1<<<NB*CH, 256>>>(x, s3d1, s5d1, d3d, d5d);

    const int PWG = NB * 64;   // 2048 blocks per GEMM: (n, 64-pixel tile)
    // merged pw wave 1: sep3-pw1(w0), sep5-pw1(w2), dil3-pw(w4, in-place), dil5-pw(w5, in-place)
    k_pw4<<<4*PWG, 256, PWM_SMEM>>>(
        p_bufA, 0, p_b4, 2,
        p_bufB, 2, p_b5, 4,
        p_b6,   4, p_b6, 6,
        p_b7,   5, p_b7, 7);

    // merged dw2: sep3 (bn s2) + sep5 (bn s4)
    k_dw2m<<<2*NB*CH, 256>>>(p_b4, s3d2, p_bufA, 2,
                             p_b5, s5d2, p_bufB, 4);

    // merged pw wave 2: sep3-pw2(w1), sep5-pw2(w3)
    k_pw4<<<2*PWG, 256, PWM_SMEM>>>(
        p_bufA, 1, p_b4, 3,
        p_bufB, 3, p_b5, 5,
        (const float*)nullptr, 0, (float*)nullptr, 0,
        (const float*)nullptr, 0, (float*)nullptr, 0);

    k_final<<<NB*CH, 256>>>(x, wts, out);
}